// round 14
// baseline (speedup 1.0000x reference)
#include <cuda_runtime.h>
#include <cstdint>
#include <cstddef>

// ---------------- problem constants ----------------
#define QL 1024
#define MLEN 1024
#define KL 2048
#define DMODEL 256
#define NH 8
#define DH 32
#define FF 1024
#define G3 768   // 3*DMODEL

typedef unsigned long long ull;

// ---------------- packed f32x2 helpers (GRU matvec only) ----------------
__device__ __forceinline__ void ffma2(ull& d, ull a, ull b) {
    asm("fma.rn.f32x2 %0, %1, %2, %0;" : "+l"(d) : "l"(a), "l"(b));
}
__device__ __forceinline__ float2 unpack2(ull v) {
    float lo, hi; asm("mov.b64 {%0,%1}, %2;" : "=f"(lo), "=f"(hi) : "l"(v));
    return make_float2(lo, hi);
}
__device__ __forceinline__ int ld_acq(const int* p) {
    int v; asm volatile("ld.acquire.gpu.global.u32 %0, [%1];" : "=r"(v) : "l"(p) : "memory");
    return v;
}
__device__ __forceinline__ void st_rel(int* p, int v) {
    asm volatile("st.release.gpu.global.u32 [%0], %1;" :: "l"(p), "r"(v) : "memory");
}

// ---------------- scratch (floats) ----------------
#define N_CAT   (KL*DMODEL)
#define N_QKV   (KL*G3)
#define N_RH    (KL*DMODEL)
#define N_QU    (NH*QL*DH)
#define N_KB    (NH*KL*DH)
#define N_SC    ((size_t)NH*QL*KL)
#define N_ROW   (QL*DMODEL)
#define N_GI    (QL*G3)
#define N_MLPH  (QL*FF)
#define N_FLG   9216   // 8192 flags1 + 1024 flags2 (as ints)

__device__ __align__(16) float g_scr[
    N_CAT + N_QKV + N_RH + 2*N_QU + 3*N_KB +
    3*N_SC +
    5*N_ROW + N_GI + 2*N_ROW + N_MLPH + 2*N_ROW + N_GI + N_FLG
];

#define OFF_CAT  ((size_t)0)
#define OFF_QKV  (OFF_CAT + N_CAT)
#define OFF_RH   (OFF_QKV + N_QKV)
#define OFF_QU   (OFF_RH  + N_RH)
#define OFF_QV   (OFF_QU  + N_QU)
#define OFF_KB   (OFF_QV  + N_QU)
#define OFF_RB   (OFF_KB  + N_KB)
#define OFF_VT   (OFF_RB  + N_KB)
#define OFF_AC   (OFF_VT  + N_KB)
#define OFF_BD   (OFF_AC  + N_SC)
#define OFF_P    (OFF_BD  + N_SC)
#define OFF_AV   (OFF_P   + N_SC)
#define OFF_Y    (OFF_AV  + N_ROW)
#define OFF_LN   (OFF_Y   + N_ROW)
#define OFF_GIN  (OFF_LN  + N_ROW)
#define OFF_GI   (OFF_GIN + N_ROW)
#define OFF_YS1  (OFF_GI  + N_GI)
#define OFF_LN2  (OFF_YS1 + N_ROW)
#define OFF_MLPH (OFF_LN2 + N_ROW)
#define OFF_MLPO (OFF_MLPH + N_MLPH)
#define OFF_GIN2 (OFF_MLPO + N_ROW)
#define OFF_GI2  (OFF_GIN2 + N_ROW)
#define OFF_FLG  (OFF_GI2  + N_GI)

// ---- fp32 SGEMM: C = A(MxK)*B(NxK)^T (+bias)(+res)(+relu); all dims tile-exact ----
#define BM 64
#define BN 64
#define BKT 32

__global__ void __launch_bounds__(256)
k_sgemm(const float* __restrict__ A, const float* __restrict__ B,
        const float* __restrict__ bias, const float* __restrict__ res,
        float* __restrict__ C,
        int K, int lda, int ldb, int ldc,
        size_t sA, size_t sB, size_t sC, int relu)
{
    int bz = blockIdx.z;
    A += (size_t)bz * sA;  B += (size_t)bz * sB;  C += (size_t)bz * sC;

    __shared__ float As[BKT][BM];
    __shared__ float Bs[BKT][BN];

    int tid = threadIdx.x;
    int row0 = blockIdx.y * BM, col0 = blockIdx.x * BN;
    int tx = tid & 15, ty = tid >> 4;
    int ar = tid >> 2;           // 0..63
    int ak = (tid & 3) * 8;      // 0,8,16,24

    const float* Aptr = A + (size_t)(row0 + ar) * lda + ak;
    const float* Bptr = B + (size_t)(col0 + ar) * ldb + ak;

    float acc[4][4];
#pragma unroll
    for (int i = 0; i < 4; i++)
#pragma unroll
        for (int j = 0; j < 4; j++) acc[i][j] = 0.f;

    int nt = K / BKT;
    for (int it = 0; it < nt; it++) {
        if (it) __syncthreads();
        float4 a0 = *(const float4*)(Aptr + (size_t)it * BKT);
        float4 a1 = *(const float4*)(Aptr + (size_t)it * BKT + 4);
        float4 b0 = *(const float4*)(Bptr + (size_t)it * BKT);
        float4 b1 = *(const float4*)(Bptr + (size_t)it * BKT + 4);
        As[ak+0][ar]=a0.x; As[ak+1][ar]=a0.y; As[ak+2][ar]=a0.z; As[ak+3][ar]=a0.w;
        As[ak+4][ar]=a1.x; As[ak+5][ar]=a1.y; As[ak+6][ar]=a1.z; As[ak+7][ar]=a1.w;
        Bs[ak+0][ar]=b0.x; Bs[ak+1][ar]=b0.y; Bs[ak+2][ar]=b0.z; Bs[ak+3][ar]=b0.w;
        Bs[ak+4][ar]=b1.x; Bs[ak+5][ar]=b1.y; Bs[ak+6][ar]=b1.z; Bs[ak+7][ar]=b1.w;
        __syncthreads();
#pragma unroll
        for (int kk = 0; kk < BKT; kk++) {
            float4 av4 = *(const float4*)&As[kk][ty*4];
            float4 bv4 = *(const float4*)&Bs[kk][tx*4];
            float a[4] = {av4.x, av4.y, av4.z, av4.w};
            float b[4] = {bv4.x, bv4.y, bv4.z, bv4.w};
#pragma unroll
            for (int i = 0; i < 4; i++)
#pragma unroll
                for (int j = 0; j < 4; j++)
                    acc[i][j] = fmaf(a[i], b[j], acc[i][j]);
        }
    }

#pragma unroll
    for (int i = 0; i < 4; i++) {
        int r = row0 + ty*4 + i;
#pragma unroll
        for (int j = 0; j < 4; j++) {
            int c = col0 + tx*4 + j;
            float v = acc[i][j];
            if (bias) v += bias[c];
            if (relu) v = v > 0.f ? v : 0.f;
            if (res)  v += res[(size_t)r * ldc + c];
            C[(size_t)r * ldc + c] = v;
        }
    }
}

// ---------------- small kernels ----------------
__global__ void k_concat(const float* __restrict__ mem, const float* __restrict__ inp,
                         float* __restrict__ cat)
{
    int idx = blockIdx.x * blockDim.x + threadIdx.x;
    int row = idx >> 8;
    cat[idx] = (row < MLEN) ? mem[idx] : inp[idx - MLEN * DMODEL];
}

__global__ void k_prep_q(const float* __restrict__ qkv, const float* __restrict__ u,
                         const float* __restrict__ v, float* __restrict__ qu,
                         float* __restrict__ qv)
{
    int idx = blockIdx.x * blockDim.x + threadIdx.x;
    int h = idx >> 15;
    int rem = idx & 32767;
    int i = rem >> 5, d = rem & 31;
    int c = (h << 5) + d;
    float val = qkv[(size_t)(MLEN + i) * G3 + c];
    qu[idx] = val + u[c];
    qv[idx] = val + v[c];
}

__global__ void k_prep_kv(const float* __restrict__ qkv, const float* __restrict__ rh,
                          float* __restrict__ kb, float* __restrict__ rb,
                          float* __restrict__ vt)
{
    int idx = blockIdx.x * blockDim.x + threadIdx.x;
    int h = idx >> 16;
    int rem = idx & 65535;
    int j = rem >> 5, d = rem & 31;
    int c = (h << 5) + d;
    kb[idx] = qkv[(size_t)j * G3 + DMODEL + c];
    rb[idx] = rh[(size_t)j * DMODEL + c];
    vt[((size_t)h << 16) + ((size_t)d << 11) + j] = qkv[(size_t)j * G3 + 2*DMODEL + c];
}

__global__ void k_ln(const float* __restrict__ in, const float* __restrict__ g,
                     const float* __restrict__ b, const float* __restrict__ res,
                     float* __restrict__ out)
{
    __shared__ float red[256];
    int row = blockIdx.x, tid = threadIdx.x;
    float x = in[(size_t)row * DMODEL + tid];
    red[tid] = x; __syncthreads();
    for (int s = 128; s > 0; s >>= 1) { if (tid < s) red[tid] += red[tid + s]; __syncthreads(); }
    float mu = red[0] * (1.f / DMODEL);
    __syncthreads();
    float dx = x - mu;
    red[tid] = dx * dx; __syncthreads();
    for (int s = 128; s > 0; s >>= 1) { if (tid < s) red[tid] += red[tid + s]; __syncthreads(); }
    float var = red[0] * (1.f / DMODEL);
    float v = dx * rsqrtf(var + 1e-5f) * g[tid] + b[tid];
    if (res) v += res[(size_t)row * DMODEL + tid];
    out[(size_t)row * DMODEL + tid] = v;
}

// ---- softmax (all 8 heads per CTA) with rel-shift + mask; writes P AND attn(i,j,h) ----
__global__ void __launch_bounds__(256)
k_softmax8(const float* __restrict__ AC, const float* __restrict__ BD,
           float* __restrict__ P, float* __restrict__ attn)
{
    extern __shared__ float sb[];     // 8 * 2048 floats (64 KB)
    __shared__ float red[256];
    int i = blockIdx.x, tid = threadIdx.x;
    int lim = i + MLEN;
    const float scale = 0.17677669529663687f;   // 1/sqrt(32)

    for (int h = 0; h < NH; h++) {
        const float* ac = AC + ((size_t)h << 21) + ((size_t)i << 11);
        const float* bd = BD + ((size_t)h << 21) + ((size_t)i << 11) + (QL - 1 - i);
        float* row = sb + (h << 11);

        float mx = -1e30f;
        for (int j = tid; j <= lim; j += 256) {
            float s = (ac[j] + bd[j]) * scale;
            row[j] = s;
            mx = fmaxf(mx, s);
        }
        red[tid] = mx; __syncthreads();
        for (int s = 128; s > 0; s >>= 1) { if (tid < s) red[tid] = fmaxf(red[tid], red[tid+s]); __syncthreads(); }
        float mxv = red[0];
        __syncthreads();

        float sum = 0.f;
        for (int j = tid; j <= lim; j += 256) {
            float e = __expf(row[j] - mxv);
            row[j] = e;
            sum += e;
        }
        red[tid] = sum; __syncthreads();
        for (int s = 128; s > 0; s >>= 1) { if (tid < s) red[tid] += red[tid+s]; __syncthreads(); }
        float inv = 1.f / red[0];
        __syncthreads();

        float* p = P + ((size_t)h << 21) + ((size_t)i << 11);
        for (int j = tid; j < KL; j += 256) {
            float v = (j <= lim) ? row[j] * inv : 0.f;
            row[j] = v;
            p[j] = v;
        }
    }
    __syncthreads();

    float* o = attn + (size_t)i * KL * NH;
    for (int j = tid; j < KL; j += 256) {
        float4 v0 = make_float4(sb[j], sb[2048 + j], sb[4096 + j], sb[6144 + j]);
        float4 v1 = make_float4(sb[8192 + j], sb[10240 + j], sb[12288 + j], sb[14336 + j]);
        float4* dst = (float4*)(o + (size_t)j * NH);
        dst[0] = v0;
        dst[1] = v1;
    }
}

// ---- AV: av[i, h*32+d] = sum_j P[h,i,j] * vt[h,d,j]; 64x32 tile, BK=32, 128 CTAs ----
__global__ void __launch_bounds__(256)
k_av(const float* __restrict__ P, const float* __restrict__ VT, float* __restrict__ AV)
{
    __shared__ float Ps[32][68];
    __shared__ float Vs[32][36];

    int bi = blockIdx.x, h = blockIdx.y;
    int i0 = bi * 64;
    int tid = threadIdx.x;
    int tx = tid & 7, ty = tid >> 3;

    const float* Ph = P  + ((size_t)h << 21);
    const float* Vh = VT + ((size_t)h << 16);

    int Kend = i0 + 64 + MLEN;
    if (Kend > KL) Kend = KL;
    int nt = Kend >> 5;

    int pr = tid >> 2;
    int pc = (tid & 3) * 8;
    int vd = tid >> 3;
    int vk = (tid & 7) * 4;

    const float* Pptr = Ph + (size_t)(i0 + pr) * KL + pc;
    const float* Vptr = Vh + (size_t)vd * KL + vk;

    float acc[2][4];
#pragma unroll
    for (int a = 0; a < 2; a++)
#pragma unroll
        for (int b = 0; b < 4; b++) acc[a][b] = 0.f;

    for (int it = 0; it < nt; it++) {
        if (it) __syncthreads();
        int j0 = it << 5;
        float4 p0 = *(const float4*)(Pptr + j0);
        float4 p1 = *(const float4*)(Pptr + j0 + 4);
        float4 v0 = *(const float4*)(Vptr + j0);
        Ps[pc+0][pr]=p0.x; Ps[pc+1][pr]=p0.y; Ps[pc+2][pr]=p0.z; Ps[pc+3][pr]=p0.w;
        Ps[pc+4][pr]=p1.x; Ps[pc+5][pr]=p1.y; Ps[pc+6][pr]=p1.z; Ps[pc+7][pr]=p1.w;
        Vs[vk+0][vd]=v0.x; Vs[vk+1][vd]=v0.y; Vs[vk+2][vd]=v0.z; Vs[vk+3][vd]=v0.w;
        __syncthreads();
#pragma unroll
        for (int kk = 0; kk < 32; kk++) {
            float2 pv = *(const float2*)&Ps[kk][ty*2];
            float4 vv = *(const float4*)&Vs[kk][tx*4];
            float pa[2] = {pv.x, pv.y};
            float vb[4] = {vv.x, vv.y, vv.z, vv.w};
#pragma unroll
            for (int a = 0; a < 2; a++)
#pragma unroll
                for (int b = 0; b < 4; b++)
                    acc[a][b] = fmaf(pa[a], vb[b], acc[a][b]);
        }
    }

#pragma unroll
    for (int a = 0; a < 2; a++) {
        int r = i0 + ty*2 + a;
#pragma unroll
        for (int b = 0; b < 4; b++) {
            int c = (h << 5) + tx*4 + b;
            AV[(size_t)r * DMODEL + c] = acc[a][b];
        }
    }
}

// ======== mega tail kernel: GRU1 ∥ per-timestep LN2/MLP/gi2 workers ∥ GRU2 ========

// GRU scan (cluster of 8 CTAs, 256 threads each; tid<192 do matvec rows).
// pub   != null : publish pub[t*8 + rank] after ys row stores (GRU1).
// gate  != null : poll gate[t] before loading gi row t (GRU2).
__device__ void gru_scan(const float* __restrict__ gi, const float* __restrict__ Whh,
                         const float* __restrict__ bhh, float* __restrict__ ys,
                         int* pub, int* gate)
{
    __shared__ float hbuf[512];
    __shared__ float ghb[96];

    int tid = threadIdx.x;
    unsigned rank;
    asm("mov.u32 %0, %%cluster_ctarank;" : "=r"(rank));

    int rr = tid >> 1, hlf = tid & 1;
    ulonglong2 w[32];
    if (tid < 192) {
        int gatei = rr >> 5, dl = rr & 31;
        int grow = gatei * 256 + (int)rank * 32 + dl;
        const ulonglong2* wp = (const ulonglong2*)(Whh + (size_t)grow * DMODEL + hlf * 128);
#pragma unroll
        for (int q = 0; q < 32; q++) w[q] = __ldg(&wp[q]);
    } else {
#pragma unroll
        for (int q = 0; q < 32; q++) { w[q].x = 0ull; w[q].y = 0ull; }
    }

    for (int i2 = tid; i2 < 512; i2 += 256) hbuf[i2] = 0.f;

    float bR = 0.f, bZ = 0.f, bN = 0.f;
    int gdim = 0;
    uint32_t hb_r[8];
    float ir = 0.f, iz = 0.f, inn = 0.f;
    if (tid < 32) {
        gdim = (int)rank * 32 + tid;
        bR = bhh[gdim]; bZ = bhh[256 + gdim]; bN = bhh[512 + gdim];
        uint32_t hb_l = (uint32_t)__cvta_generic_to_shared((void*)hbuf);
#pragma unroll
        for (int p = 0; p < 8; p++) {
            asm("mapa.shared::cluster.u32 %0, %1, %2;" : "=r"(hb_r[p]) : "r"(hb_l), "r"(p));
        }
        if (gate) { while (!ld_acq(gate + 0)) {} }
        ir  = gi[gdim];
        iz  = gi[256 + gdim];
        inn = gi[512 + gdim];
    }
    __syncthreads();
    asm volatile("barrier.cluster.arrive.aligned;" ::: "memory");
    asm volatile("barrier.cluster.wait.aligned;" ::: "memory");

#pragma unroll 1
    for (int t = 0; t < QL; t++) {
        float hprev = 0.f;
        if (tid < 32) hprev = hbuf[(t & 1) * 256 + gdim];

        const ulonglong2* h2 = (const ulonglong2*)(hbuf + (t & 1) * 256 + hlf * 128);
        ull acc0 = 0ull, acc1 = 0ull;
#pragma unroll
        for (int q = 0; q < 32; q++) {
            ulonglong2 hv = h2[q];
            ffma2(acc0, w[q].x, hv.x);
            ffma2(acc1, w[q].y, hv.y);
        }
        float2 a0 = unpack2(acc0), a1 = unpack2(acc1);
        float sum = (a0.x + a0.y) + (a1.x + a1.y);
        sum += __shfl_down_sync(0xffffffffu, sum, 1);
        if (!hlf && rr < 96) ghb[rr] = sum;
        __syncthreads();

        float hnew = 0.f;
        if (tid < 32) {
            float hr = ghb[tid]      + bR;
            float hz = ghb[32 + tid] + bZ;
            float hn = ghb[64 + tid] + bN;
            float xr = ir + hr, xz = iz + hz;
            float rg = __fdividef(1.f, 1.f + __expf(-xr));
            float zg = __fdividef(1.f, 1.f + __expf(-xz));
            float xn = inn + rg * hn;
            float en = __expf(-2.f * fabsf(xn));
            float tg = (1.f - en) * __fdividef(1.f, 1.f + en);
            float ng = (xn >= 0.f) ? tg : -tg;
            hnew = (1.f - zg) * ng + zg * hprev;
            if (t < QL - 1) {
                uint32_t off = (uint32_t)(((t + 1) & 1) * 256 + gdim) * 4u;
#pragma unroll
                for (int p = 0; p < 8; p++) {
                    asm volatile("st.shared::cluster.f32 [%0], %1;"
                                 :: "r"(hb_r[p] + off), "f"(hnew) : "memory");
                }
            }
        }
        asm volatile("barrier.cluster.arrive.aligned;" ::: "memory");
        if (tid < 32) {
            ys[(size_t)t * DMODEL + gdim] = hnew;
            if (pub) {
                __syncwarp();
                if (tid == 0) st_rel(pub + t * 8 + (int)rank, 1);
            }
            if (t + 1 < QL) {
                if (gate) { while (!ld_acq(gate + t + 1)) {} }
                const float* g = gi + (size_t)(t + 1) * G3;
                ir  = g[gdim];
                iz  = g[256 + gdim];
                inn = g[512 + gdim];
            }
        }
        asm volatile("barrier.cluster.wait.aligned;" ::: "memory");
    }
}

// per-timestep worker: LN2 -> MLP -> +residual -> gi2 row; 1 CTA per timestep
__device__ void worker_loop(int wkr,
    const float* __restrict__ ys1, const float* __restrict__ ln2_g, const float* __restrict__ ln2_b,
    const float* __restrict__ W1, const float* __restrict__ b1,
    const float* __restrict__ W2, const float* __restrict__ b2,
    const float* __restrict__ g2_Wih, const float* __restrict__ g2_bih,
    float* __restrict__ gi2, int* flags1, int* flags2)
{
    __shared__ float xs[256];
    __shared__ float h1s[1024];
    __shared__ float gins[256];
    __shared__ float red[256];
    int tid = threadIdx.x;

#pragma unroll 1
    for (int t = wkr; t < QL; t += 128) {
        if (tid < 8) {
            while (!ld_acq(flags1 + t * 8 + tid)) { __nanosleep(64); }
        }
        __syncthreads();

        float x = ys1[(size_t)t * DMODEL + tid];
        // LN2 (same reduction structure as k_ln)
        red[tid] = x; __syncthreads();
        for (int s = 128; s > 0; s >>= 1) { if (tid < s) red[tid] += red[tid + s]; __syncthreads(); }
        float mu = red[0] * (1.f / DMODEL);
        __syncthreads();
        float dx = x - mu;
        red[tid] = dx * dx; __syncthreads();
        for (int s = 128; s > 0; s >>= 1) { if (tid < s) red[tid] += red[tid + s]; __syncthreads(); }
        float var = red[0] * (1.f / DMODEL);
        xs[tid] = dx * rsqrtf(var + 1e-5f) * ln2_g[tid] + ln2_b[tid];
        __syncthreads();

        // MLP layer 1: each thread computes 4 FF dims
#pragma unroll
        for (int q = 0; q < 4; q++) {
            int f = tid + 256 * q;
            const float4* wr = (const float4*)(W1 + (size_t)f * DMODEL);
            float a0 = 0.f, a1 = 0.f, a2 = 0.f, a3 = 0.f;
#pragma unroll 8
            for (int k = 0; k < 64; k++) {
                float4 wv = wr[k];
                float4 xv = *(const float4*)&xs[k * 4];
                a0 = fmaf(wv.x, xv.x, a0); a1 = fmaf(wv.y, xv.y, a1);
                a2 = fmaf(wv.z, xv.z, a2); a3 = fmaf(wv.w, xv.w, a3);
            }
            float hv = b1[f] + ((a0 + a1) + (a2 + a3));
            h1s[f] = hv > 0.f ? hv : 0.f;
        }
        __syncthreads();

        // MLP layer 2 + residual
        {
            const float4* wr = (const float4*)(W2 + (size_t)tid * FF);
            float a0 = 0.f, a1 = 0.f, a2 = 0.f, a3 = 0.f;
#pragma unroll 8
            for (int k = 0; k < 256; k++) {
                float4 wv = wr[k];
                float4 hv = *(const float4*)&h1s[k * 4];
                a0 = fmaf(wv.x, hv.x, a0); a1 = fmaf(wv.y, hv.y, a1);
                a2 = fmaf(wv.z, hv.z, a2); a3 = fmaf(wv.w, hv.w, a3);
            }
            gins[tid] = x + b2[tid] + ((a0 + a1) + (a2 + a3));
        }
        __syncthreads();

        // gi2 row: each thread computes 3 gate dims
#pragma unroll
        for (int q = 0; q < 3; q++) {
            int g = tid + 256 * q;
            const float4* wr = (const float4*)(g2_Wih + (size_t)g * DMODEL);
            float a0 = 0.f, a1 = 0.f, a2 = 0.f, a3 = 0.f;
#pragma unroll 8
            for (int k = 0; k < 64; k++) {
                float4 wv = wr[k];
                float4 gv = *(const float4*)&gins[k * 4];
                a0 = fmaf(wv.x, gv.x, a0); a1 = fmaf(wv.y, gv.y, a1);
                a2 = fmaf(wv.z, gv.z, a2); a3 = fmaf(wv.w, gv.w, a3);
            }
            gi2[(size_t)t * G3 + g] = g2_bih[g] + ((a0 + a1) + (a2 + a3));
        }
        __syncthreads();
        if (tid == 0) st_rel(flags2 + t, 1);
    }
}

__global__ void __launch_bounds__(256, 1) __cluster_dims__(8, 1, 1)
k_tail(const float* __restrict__ gi1, const float* __restrict__ g1_Whh,
       const float* __restrict__ g1_bhh, float* __restrict__ ys1,
       const float* __restrict__ ln2_g, const float* __restrict__ ln2_b,
       const float* __restrict__ W1, const float* __restrict__ b1,
       const float* __restrict__ W2, const float* __restrict__ b2,
       const float* __restrict__ g2_Wih, const float* __restrict__ g2_bih,
       const float* __restrict__ g2_Whh, const float* __restrict__ g2_bhh,
       float* __restrict__ gi2, float* __restrict__ out_y,
       int* flags1, int* flags2)
{
    int cid = blockIdx.x >> 3;
    if (cid == 0) {
        gru_scan(gi1, g1_Whh, g1_bhh, ys1, flags1, nullptr);
    } else if (cid == 1) {
        gru_scan(gi2, g2_Whh, g2_bhh, out_y, nullptr, flags2);
    } else {
        worker_loop(blockIdx.x - 16, ys1, ln2_g, ln2_b, W1, b1, W2, b2,
                    g2_Wih, g2_bih, gi2, flags1, flags2);
    }
}

// ---------------- host orchestration ----------------
extern "C" void kernel_launch(void* const* d_in, const int* in_sizes, int n_in,
                              void* d_out, int out_size) {
    const float* inputs = (const float*)d_in[0];
    const float* r      = (const float*)d_in[1];
    const float* u      = (const float*)d_in[2];
    const float* v      = (const float*)d_in[3];
    const float* mem    = (const float*)d_in[4];
    const float* ln1_g  = (const float*)d_in[5];
    const float* ln1_b  = (const float*)d_in[6];
    const float* ln2_g  = (const float*)d_in[7];
    const float* ln2_b  = (const float*)d_in[8];
    const float* Wqkv   = (const float*)d_in[9];
    const float* bqkv   = (const float*)d_in[10];
    const float* Wr     = (const float*)d_in[11];
    const float* Wo     = (const float*)d_in[12];
    const float* bo     = (const float*)d_in[13];
    const float* g1_Wih = (const float*)d_in[14];
    const float* g1_Whh = (const float*)d_in[15];
    const float* g1_bih = (const float*)d_in[16];
    const float* g1_bhh = (const float*)d_in[17];
    const float* g2_Wih = (const float*)d_in[18];
    const float* g2_Whh = (const float*)d_in[19];
    const float* g2_bih = (const float*)d_in[20];
    const float* g2_bhh = (const float*)d_in[21];
    const float* W1     = (const float*)d_in[22];
    const float* b1     = (const float*)d_in[23];
    const float* W2     = (const float*)d_in[24];
    const float* b2     = (const float*)d_in[25];

    float* scr = nullptr;
    cudaGetSymbolAddress((void**)&scr, g_scr);

    float* CAT  = scr + OFF_CAT;
    float* QKV  = scr + OFF_QKV;
    float* RH   = scr + OFF_RH;
    float* QU   = scr + OFF_QU;
    float* QV   = scr + OFF_QV;
    float* KB   = scr + OFF_KB;
    float* RB   = scr + OFF_RB;
    float* VT   = scr + OFF_VT;
    float* AC   = scr + OFF_AC;
    float* BD   = scr + OFF_BD;
    float* P    = scr + OFF_P;
    float* AV   = scr + OFF_AV;
    float* Y    = scr + OFF_Y;
    float* GIN  = scr + OFF_GIN;
    float* GI   = scr + OFF_GI;
    float* YS1  = scr + OFF_YS1;
    float* GI2  = scr + OFF_GI2;
    int*   FLG1 = (int*)(scr + OFF_FLG);
    int*   FLG2 = FLG1 + 8192;

    float* out_y    = (float*)d_out;
    float* out_attn = (float*)d_out + (size_t)QL * DMODEL;

    static int smax_cfg = 0;
    if (!smax_cfg) {
        cudaFuncSetAttribute(k_softmax8, cudaFuncAttributeMaxDynamicSharedMemorySize,
                             NH * KL * (int)sizeof(float));
        smax_cfg = 1;
    }

    // reset pipeline flags (graph-capturable async memset)
    cudaMemsetAsync(FLG1, 0, N_FLG * sizeof(int));

    k_concat<<<(KL*DMODEL)/256, 256>>>(mem, inputs, CAT);
    k_sgemm<<<dim3(G3/BN, KL/BM, 1), 256>>>(CAT, Wqkv, bqkv, nullptr, QKV,
        DMODEL, DMODEL, DMODEL, G3, 0, 0, 0, 0);
    k_sgemm<<<dim3(DMODEL/BN, KL/BM, 1), 256>>>(r, Wr, nullptr, nullptr, RH,
        DMODEL, DMODEL, DMODEL, DMODEL, 0, 0, 0, 0);
    k_prep_q<<<(NH*QL*DH)/256, 256>>>(QKV, u, v, QU, QV);
    k_prep_kv<<<(NH*KL*DH)/256, 256>>>(QKV, RH, KB, RB, VT);
    k_sgemm<<<dim3(KL/BN, QL/BM, NH), 256>>>(QU, KB, nullptr, nullptr, AC,
        DH, DH, DH, KL, (size_t)QL*DH, (size_t)KL*DH, (size_t)QL*KL, 0);
    k_sgemm<<<dim3(KL/BN, QL/BM, NH), 256>>>(QV, RB, nullptr, nullptr, BD,
        DH, DH, DH, KL, (size_t)QL*DH, (size_t)KL*DH, (size_t)QL*KL, 0);
    k_softmax8<<<QL, 256, NH*KL*sizeof(float)>>>(AC, BD, P, out_attn);
    k_av<<<dim3(QL/64, NH), 256>>>(P, VT, AV);
    k_sgemm<<<dim3(DMODEL/BN, QL/BM, 1), 256>>>(AV, Wo, bo, nullptr, Y,
        DMODEL, DMODEL, DMODEL, DMODEL, 0, 0, 0, 0);
    k_ln<<<QL, 256>>>(Y, ln1_g, ln1_b, inputs, GIN);
    k_sgemm<<<dim3(G3/BN, QL/BM, 1), 256>>>(GIN, g1_Wih, g1_bih, nullptr, GI,
        DMODEL, DMODEL, DMODEL, G3, 0, 0, 0, 0);
    // pipelined tail: GRU1 || per-timestep LN2/MLP/gi2 workers || GRU2
    k_tail<<<144, 256>>>(GI, g1_Whh, g1_bhh, YS1,
                         ln2_g, ln2_b, W1, b1, W2, b2,
                         g2_Wih, g2_bih, g2_Whh, g2_bhh,
                         GI2, out_y, FLG1, FLG2);
}

// round 15
// speedup vs baseline: 1.0867x; 1.0867x over previous
#include <cuda_runtime.h>
#include <cstdint>
#include <cstddef>

// ---------------- problem constants ----------------
#define QL 1024
#define MLEN 1024
#define KL 2048
#define DMODEL 256
#define NH 8
#define DH 32
#define FF 1024
#define G3 768   // 3*DMODEL

typedef unsigned long long ull;

// ---------------- packed f32x2 helpers (GRU matvec only) ----------------
__device__ __forceinline__ void ffma2(ull& d, ull a, ull b) {
    asm("fma.rn.f32x2 %0, %1, %2, %0;" : "+l"(d) : "l"(a), "l"(b));
}
__device__ __forceinline__ float2 unpack2(ull v) {
    float lo, hi; asm("mov.b64 {%0,%1}, %2;" : "=f"(lo), "=f"(hi) : "l"(v));
    return make_float2(lo, hi);
}
__device__ __forceinline__ int ld_acq(const int* p) {
    int v; asm volatile("ld.acquire.gpu.global.u32 %0, [%1];" : "=r"(v) : "l"(p) : "memory");
    return v;
}
__device__ __forceinline__ void st_rel(int* p, int v) {
    asm volatile("st.release.gpu.global.u32 [%0], %1;" :: "l"(p), "r"(v) : "memory");
}

// ---------------- scratch (floats) ----------------
#define N_CAT   (KL*DMODEL)
#define N_QKV   (KL*G3)
#define N_RH    (KL*DMODEL)
#define N_QU    (NH*QL*DH)
#define N_KB    (NH*KL*DH)
#define N_SC    ((size_t)NH*QL*KL)
#define N_ROW   (QL*DMODEL)
#define N_GI    (QL*G3)
#define N_MLPH  (QL*FF)
#define N_FLG   (8*32 + QL*32)   // padded rank counters + padded per-t flags

__device__ __align__(16) float g_scr[
    N_CAT + N_QKV + N_RH + 2*N_QU + 3*N_KB +
    3*N_SC +
    5*N_ROW + N_GI + 2*N_ROW + N_MLPH + 2*N_ROW + N_GI + N_FLG
];

#define OFF_CAT  ((size_t)0)
#define OFF_QKV  (OFF_CAT + N_CAT)
#define OFF_RH   (OFF_QKV + N_QKV)
#define OFF_QU   (OFF_RH  + N_RH)
#define OFF_QV   (OFF_QU  + N_QU)
#define OFF_KB   (OFF_QV  + N_QU)
#define OFF_RB   (OFF_KB  + N_KB)
#define OFF_VT   (OFF_RB  + N_KB)
#define OFF_AC   (OFF_VT  + N_KB)
#define OFF_BD   (OFF_AC  + N_SC)
#define OFF_P    (OFF_BD  + N_SC)
#define OFF_AV   (OFF_P   + N_SC)
#define OFF_Y    (OFF_AV  + N_ROW)
#define OFF_LN   (OFF_Y   + N_ROW)
#define OFF_GIN  (OFF_LN  + N_ROW)
#define OFF_GI   (OFF_GIN + N_ROW)
#define OFF_YS1  (OFF_GI  + N_GI)
#define OFF_LN2  (OFF_YS1 + N_ROW)
#define OFF_MLPH (OFF_LN2 + N_ROW)
#define OFF_MLPO (OFF_MLPH + N_MLPH)
#define OFF_GIN2 (OFF_MLPO + N_ROW)
#define OFF_GI2  (OFF_GIN2 + N_ROW)
#define OFF_FLG  (OFF_GI2  + N_GI)

// ---- fp32 SGEMM: C = A(MxK)*B(NxK)^T (+bias)(+res)(+relu); all dims tile-exact ----
#define BM 64
#define BN 64
#define BKT 32

__global__ void __launch_bounds__(256)
k_sgemm(const float* __restrict__ A, const float* __restrict__ B,
        const float* __restrict__ bias, const float* __restrict__ res,
        float* __restrict__ C,
        int K, int lda, int ldb, int ldc,
        size_t sA, size_t sB, size_t sC, int relu)
{
    int bz = blockIdx.z;
    A += (size_t)bz * sA;  B += (size_t)bz * sB;  C += (size_t)bz * sC;

    __shared__ float As[BKT][BM];
    __shared__ float Bs[BKT][BN];

    int tid = threadIdx.x;
    int row0 = blockIdx.y * BM, col0 = blockIdx.x * BN;
    int tx = tid & 15, ty = tid >> 4;
    int ar = tid >> 2;           // 0..63
    int ak = (tid & 3) * 8;      // 0,8,16,24

    const float* Aptr = A + (size_t)(row0 + ar) * lda + ak;
    const float* Bptr = B + (size_t)(col0 + ar) * ldb + ak;

    float acc[4][4];
#pragma unroll
    for (int i = 0; i < 4; i++)
#pragma unroll
        for (int j = 0; j < 4; j++) acc[i][j] = 0.f;

    int nt = K / BKT;
    for (int it = 0; it < nt; it++) {
        if (it) __syncthreads();
        float4 a0 = *(const float4*)(Aptr + (size_t)it * BKT);
        float4 a1 = *(const float4*)(Aptr + (size_t)it * BKT + 4);
        float4 b0 = *(const float4*)(Bptr + (size_t)it * BKT);
        float4 b1 = *(const float4*)(Bptr + (size_t)it * BKT + 4);
        As[ak+0][ar]=a0.x; As[ak+1][ar]=a0.y; As[ak+2][ar]=a0.z; As[ak+3][ar]=a0.w;
        As[ak+4][ar]=a1.x; As[ak+5][ar]=a1.y; As[ak+6][ar]=a1.z; As[ak+7][ar]=a1.w;
        Bs[ak+0][ar]=b0.x; Bs[ak+1][ar]=b0.y; Bs[ak+2][ar]=b0.z; Bs[ak+3][ar]=b0.w;
        Bs[ak+4][ar]=b1.x; Bs[ak+5][ar]=b1.y; Bs[ak+6][ar]=b1.z; Bs[ak+7][ar]=b1.w;
        __syncthreads();
#pragma unroll
        for (int kk = 0; kk < BKT; kk++) {
            float4 av4 = *(const float4*)&As[kk][ty*4];
            float4 bv4 = *(const float4*)&Bs[kk][tx*4];
            float a[4] = {av4.x, av4.y, av4.z, av4.w};
            float b[4] = {bv4.x, bv4.y, bv4.z, bv4.w};
#pragma unroll
            for (int i = 0; i < 4; i++)
#pragma unroll
                for (int j = 0; j < 4; j++)
                    acc[i][j] = fmaf(a[i], b[j], acc[i][j]);
        }
    }

#pragma unroll
    for (int i = 0; i < 4; i++) {
        int r = row0 + ty*4 + i;
#pragma unroll
        for (int j = 0; j < 4; j++) {
            int c = col0 + tx*4 + j;
            float v = acc[i][j];
            if (bias) v += bias[c];
            if (relu) v = v > 0.f ? v : 0.f;
            if (res)  v += res[(size_t)r * ldc + c];
            C[(size_t)r * ldc + c] = v;
        }
    }
}

// ---------------- small kernels ----------------
__global__ void k_concat(const float* __restrict__ mem, const float* __restrict__ inp,
                         float* __restrict__ cat)
{
    int idx = blockIdx.x * blockDim.x + threadIdx.x;
    int row = idx >> 8;
    cat[idx] = (row < MLEN) ? mem[idx] : inp[idx - MLEN * DMODEL];
}

__global__ void k_prep_q(const float* __restrict__ qkv, const float* __restrict__ u,
                         const float* __restrict__ v, float* __restrict__ qu,
                         float* __restrict__ qv)
{
    int idx = blockIdx.x * blockDim.x + threadIdx.x;
    int h = idx >> 15;
    int rem = idx & 32767;
    int i = rem >> 5, d = rem & 31;
    int c = (h << 5) + d;
    float val = qkv[(size_t)(MLEN + i) * G3 + c];
    qu[idx] = val + u[c];
    qv[idx] = val + v[c];
}

__global__ void k_prep_kv(const float* __restrict__ qkv, const float* __restrict__ rh,
                          float* __restrict__ kb, float* __restrict__ rb,
                          float* __restrict__ vt)
{
    int idx = blockIdx.x * blockDim.x + threadIdx.x;
    int h = idx >> 16;
    int rem = idx & 65535;
    int j = rem >> 5, d = rem & 31;
    int c = (h << 5) + d;
    kb[idx] = qkv[(size_t)j * G3 + DMODEL + c];
    rb[idx] = rh[(size_t)j * DMODEL + c];
    vt[((size_t)h << 16) + ((size_t)d << 11) + j] = qkv[(size_t)j * G3 + 2*DMODEL + c];
}

__global__ void k_ln(const float* __restrict__ in, const float* __restrict__ g,
                     const float* __restrict__ b, const float* __restrict__ res,
                     float* __restrict__ out)
{
    __shared__ float red[256];
    int row = blockIdx.x, tid = threadIdx.x;
    float x = in[(size_t)row * DMODEL + tid];
    red[tid] = x; __syncthreads();
    for (int s = 128; s > 0; s >>= 1) { if (tid < s) red[tid] += red[tid + s]; __syncthreads(); }
    float mu = red[0] * (1.f / DMODEL);
    __syncthreads();
    float dx = x - mu;
    red[tid] = dx * dx; __syncthreads();
    for (int s = 128; s > 0; s >>= 1) { if (tid < s) red[tid] += red[tid + s]; __syncthreads(); }
    float var = red[0] * (1.f / DMODEL);
    float v = dx * rsqrtf(var + 1e-5f) * g[tid] + b[tid];
    if (res) v += res[(size_t)row * DMODEL + tid];
    out[(size_t)row * DMODEL + tid] = v;
}

// ---- softmax (all 8 heads per CTA) with rel-shift + mask; writes P AND attn(i,j,h) ----
__global__ void __launch_bounds__(256)
k_softmax8(const float* __restrict__ AC, const float* __restrict__ BD,
           float* __restrict__ P, float* __restrict__ attn)
{
    extern __shared__ float sb[];     // 8 * 2048 floats (64 KB)
    __shared__ float red[256];
    int i = blockIdx.x, tid = threadIdx.x;
    int lim = i + MLEN;
    const float scale = 0.17677669529663687f;   // 1/sqrt(32)

    for (int h = 0; h < NH; h++) {
        const float* ac = AC + ((size_t)h << 21) + ((size_t)i << 11);
        const float* bd = BD + ((size_t)h << 21) + ((size_t)i << 11) + (QL - 1 - i);
        float* row = sb + (h << 11);

        float mx = -1e30f;
        for (int j = tid; j <= lim; j += 256) {
            float s = (ac[j] + bd[j]) * scale;
            row[j] = s;
            mx = fmaxf(mx, s);
        }
        red[tid] = mx; __syncthreads();
        for (int s = 128; s > 0; s >>= 1) { if (tid < s) red[tid] = fmaxf(red[tid], red[tid+s]); __syncthreads(); }
        float mxv = red[0];
        __syncthreads();

        float sum = 0.f;
        for (int j = tid; j <= lim; j += 256) {
            float e = __expf(row[j] - mxv);
            row[j] = e;
            sum += e;
        }
        red[tid] = sum; __syncthreads();
        for (int s = 128; s > 0; s >>= 1) { if (tid < s) red[tid] += red[tid+s]; __syncthreads(); }
        float inv = 1.f / red[0];
        __syncthreads();

        float* p = P + ((size_t)h << 21) + ((size_t)i << 11);
        for (int j = tid; j < KL; j += 256) {
            float v = (j <= lim) ? row[j] * inv : 0.f;
            row[j] = v;
            p[j] = v;
        }
    }
    __syncthreads();

    float* o = attn + (size_t)i * KL * NH;
    for (int j = tid; j < KL; j += 256) {
        float4 v0 = make_float4(sb[j], sb[2048 + j], sb[4096 + j], sb[6144 + j]);
        float4 v1 = make_float4(sb[8192 + j], sb[10240 + j], sb[12288 + j], sb[14336 + j]);
        float4* dst = (float4*)(o + (size_t)j * NH);
        dst[0] = v0;
        dst[1] = v1;
    }
}

// ---- AV: av[i, h*32+d] = sum_j P[h,i,j] * vt[h,d,j]; 64x32 tile, BK=32, 128 CTAs ----
__global__ void __launch_bounds__(256)
k_av(const float* __restrict__ P, const float* __restrict__ VT, float* __restrict__ AV)
{
    __shared__ float Ps[32][68];
    __shared__ float Vs[32][36];

    int bi = blockIdx.x, h = blockIdx.y;
    int i0 = bi * 64;
    int tid = threadIdx.x;
    int tx = tid & 7, ty = tid >> 3;

    const float* Ph = P  + ((size_t)h << 21);
    const float* Vh = VT + ((size_t)h << 16);

    int Kend = i0 + 64 + MLEN;
    if (Kend > KL) Kend = KL;
    int nt = Kend >> 5;

    int pr = tid >> 2;
    int pc = (tid & 3) * 8;
    int vd = tid >> 3;
    int vk = (tid & 7) * 4;

    const float* Pptr = Ph + (size_t)(i0 + pr) * KL + pc;
    const float* Vptr = Vh + (size_t)vd * KL + vk;

    float acc[2][4];
#pragma unroll
    for (int a = 0; a < 2; a++)
#pragma unroll
        for (int b = 0; b < 4; b++) acc[a][b] = 0.f;

    for (int it = 0; it < nt; it++) {
        if (it) __syncthreads();
        int j0 = it << 5;
        float4 p0 = *(const float4*)(Pptr + j0);
        float4 p1 = *(const float4*)(Pptr + j0 + 4);
        float4 v0 = *(const float4*)(Vptr + j0);
        Ps[pc+0][pr]=p0.x; Ps[pc+1][pr]=p0.y; Ps[pc+2][pr]=p0.z; Ps[pc+3][pr]=p0.w;
        Ps[pc+4][pr]=p1.x; Ps[pc+5][pr]=p1.y; Ps[pc+6][pr]=p1.z; Ps[pc+7][pr]=p1.w;
        Vs[vk+0][vd]=v0.x; Vs[vk+1][vd]=v0.y; Vs[vk+2][vd]=v0.z; Vs[vk+3][vd]=v0.w;
        __syncthreads();
#pragma unroll
        for (int kk = 0; kk < 32; kk++) {
            float2 pv = *(const float2*)&Ps[kk][ty*2];
            float4 vv = *(const float4*)&Vs[kk][tx*4];
            float pa[2] = {pv.x, pv.y};
            float vb[4] = {vv.x, vv.y, vv.z, vv.w};
#pragma unroll
            for (int a = 0; a < 2; a++)
#pragma unroll
                for (int b = 0; b < 4; b++)
                    acc[a][b] = fmaf(pa[a], vb[b], acc[a][b]);
        }
    }

#pragma unroll
    for (int a = 0; a < 2; a++) {
        int r = i0 + ty*2 + a;
#pragma unroll
        for (int b = 0; b < 4; b++) {
            int c = (h << 5) + tx*4 + b;
            AV[(size_t)r * DMODEL + c] = acc[a][b];
        }
    }
}

// ======== pipelined tail: GRU1 ∥ per-timestep LN2/MLP/gi2 workers ∥ GRU2 ========
#define NWORK 48

// GRU scan (cluster of 8 CTAs, 256 threads; tid<192 do matvec rows).
// pub  != null : publish per-rank row counter (padded line) every 4th step.
// gate != null : single-poller per CTA on padded per-t flag before loading gi row t.
__device__ void gru_scan(const float* __restrict__ gi, const float* __restrict__ Whh,
                         const float* __restrict__ bhh, float* __restrict__ ys,
                         int* pub, int* gate)
{
    __shared__ float hbuf[512];
    __shared__ float ghb[96];

    int tid = threadIdx.x;
    unsigned rank;
    asm("mov.u32 %0, %%cluster_ctarank;" : "=r"(rank));

    int rr = tid >> 1, hlf = tid & 1;
    ulonglong2 w[32];
    if (tid < 192) {
        int gatei = rr >> 5, dl = rr & 31;
        int grow = gatei * 256 + (int)rank * 32 + dl;
        const ulonglong2* wp = (const ulonglong2*)(Whh + (size_t)grow * DMODEL + hlf * 128);
#pragma unroll
        for (int q = 0; q < 32; q++) w[q] = __ldg(&wp[q]);
    } else {
#pragma unroll
        for (int q = 0; q < 32; q++) { w[q].x = 0ull; w[q].y = 0ull; }
    }

    for (int i2 = tid; i2 < 512; i2 += 256) hbuf[i2] = 0.f;

    float bR = 0.f, bZ = 0.f, bN = 0.f;
    int gdim = 0;
    uint32_t hb_r[8];
    float ir = 0.f, iz = 0.f, inn = 0.f;
    if (tid < 32) {
        gdim = (int)rank * 32 + tid;
        bR = bhh[gdim]; bZ = bhh[256 + gdim]; bN = bhh[512 + gdim];
        uint32_t hb_l = (uint32_t)__cvta_generic_to_shared((void*)hbuf);
#pragma unroll
        for (int p = 0; p < 8; p++) {
            asm("mapa.shared::cluster.u32 %0, %1, %2;" : "=r"(hb_r[p]) : "r"(hb_l), "r"(p));
        }
        if (gate) {
            if (tid == 0) { while (!ld_acq(gate + 0)) __nanosleep(64); }
            __syncwarp();
        }
        ir  = gi[gdim];
        iz  = gi[256 + gdim];
        inn = gi[512 + gdim];
    }
    __syncthreads();
    asm volatile("barrier.cluster.arrive.aligned;" ::: "memory");
    asm volatile("barrier.cluster.wait.aligned;" ::: "memory");

#pragma unroll 1
    for (int t = 0; t < QL; t++) {
        float hprev = 0.f;
        if (tid < 32) hprev = hbuf[(t & 1) * 256 + gdim];

        const ulonglong2* h2 = (const ulonglong2*)(hbuf + (t & 1) * 256 + hlf * 128);
        ull acc0 = 0ull, acc1 = 0ull;
#pragma unroll
        for (int q = 0; q < 32; q++) {
            ulonglong2 hv = h2[q];
            ffma2(acc0, w[q].x, hv.x);
            ffma2(acc1, w[q].y, hv.y);
        }
        float2 a0 = unpack2(acc0), a1 = unpack2(acc1);
        float sum = (a0.x + a0.y) + (a1.x + a1.y);
        sum += __shfl_down_sync(0xffffffffu, sum, 1);
        if (!hlf && rr < 96) ghb[rr] = sum;
        __syncthreads();

        float hnew = 0.f;
        if (tid < 32) {
            float hr = ghb[tid]      + bR;
            float hz = ghb[32 + tid] + bZ;
            float hn = ghb[64 + tid] + bN;
            float xr = ir + hr, xz = iz + hz;
            float rg = __fdividef(1.f, 1.f + __expf(-xr));
            float zg = __fdividef(1.f, 1.f + __expf(-xz));
            float xn = inn + rg * hn;
            float en = __expf(-2.f * fabsf(xn));
            float tg = (1.f - en) * __fdividef(1.f, 1.f + en);
            float ng = (xn >= 0.f) ? tg : -tg;
            hnew = (1.f - zg) * ng + zg * hprev;
            if (t < QL - 1) {
                uint32_t off = (uint32_t)(((t + 1) & 1) * 256 + gdim) * 4u;
#pragma unroll
                for (int p = 0; p < 8; p++) {
                    asm volatile("st.shared::cluster.f32 [%0], %1;"
                                 :: "r"(hb_r[p] + off), "f"(hnew) : "memory");
                }
            }
        }
        asm volatile("barrier.cluster.arrive.aligned;" ::: "memory");
        if (tid < 32) {
            ys[(size_t)t * DMODEL + gdim] = hnew;
            if (pub && ((t & 3) == 3 || t == QL - 1)) {
                __syncwarp();
                if (tid == 0) st_rel(pub + (int)rank * 32, t + 1);
            }
            if (t + 1 < QL) {
                if (gate) {
                    if (tid == 0) {
                        while (!ld_acq(gate + (size_t)(t + 1) * 32)) __nanosleep(64);
                    }
                    __syncwarp();
                }
                const float* g = gi + (size_t)(t + 1) * G3;
                ir  = g[gdim];
                iz  = g[256 + gdim];
                inn = g[512 + gdim];
            }
        }
        asm volatile("barrier.cluster.wait.aligned;" ::: "memory");
    }
}

// per-timestep worker: LN2 -> MLP -> +residual -> gi2 row
__device__ void worker_loop(int wkr,
    const float* __restrict__ ys1, const float* __restrict__ ln2_g, const float* __restrict__ ln2_b,
    const float* __restrict__ W1, const float* __restrict__ b1,
    const float* __restrict__ W2, const float* __restrict__ b2,
    const float* __restrict__ g2_Wih, const float* __restrict__ g2_bih,
    float* __restrict__ gi2, int* flags1, int* flags2)
{
    __shared__ float xs[256];
    __shared__ float h1s[1024];
    __shared__ float gins[256];
    __shared__ float red[256];
    int tid = threadIdx.x;

#pragma unroll 1
    for (int t = wkr; t < QL; t += NWORK) {
        if (tid < 8) {
            while (ld_acq(flags1 + tid * 32) < t + 1) { __nanosleep(128); }
        }
        __syncthreads();

        float x = ys1[(size_t)t * DMODEL + tid];
        red[tid] = x; __syncthreads();
        for (int s = 128; s > 0; s >>= 1) { if (tid < s) red[tid] += red[tid + s]; __syncthreads(); }
        float mu = red[0] * (1.f / DMODEL);
        __syncthreads();
        float dx = x - mu;
        red[tid] = dx * dx; __syncthreads();
        for (int s = 128; s > 0; s >>= 1) { if (tid < s) red[tid] += red[tid + s]; __syncthreads(); }
        float var = red[0] * (1.f / DMODEL);
        xs[tid] = dx * rsqrtf(var + 1e-5f) * ln2_g[tid] + ln2_b[tid];
        __syncthreads();

#pragma unroll
        for (int q = 0; q < 4; q++) {
            int f = tid + 256 * q;
            const float4* wr = (const float4*)(W1 + (size_t)f * DMODEL);
            float a0 = 0.f, a1 = 0.f, a2 = 0.f, a3 = 0.f;
#pragma unroll 8
            for (int k = 0; k < 64; k++) {
                float4 wv = wr[k];
                float4 xv = *(const float4*)&xs[k * 4];
                a0 = fmaf(wv.x, xv.x, a0); a1 = fmaf(wv.y, xv.y, a1);
                a2 = fmaf(wv.z, xv.z, a2); a3 = fmaf(wv.w, xv.w, a3);
            }
            float hv = b1[f] + ((a0 + a1) + (a2 + a3));
            h1s[f] = hv > 0.f ? hv : 0.f;
        }
        __syncthreads();

        {
            const float4* wr = (const float4*)(W2 + (size_t)tid * FF);
            float a0 = 0.f, a1 = 0.f, a2 = 0.f, a3 = 0.f;
#pragma unroll 8
            for (int k = 0; k < 256; k++) {
                float4 wv = wr[k];
                float4 hv = *(const float4*)&h1s[k * 4];
                a0 = fmaf(wv.x, hv.x, a0); a1 = fmaf(wv.y, hv.y, a1);
                a2 = fmaf(wv.z, hv.z, a2); a3 = fmaf(wv.w, hv.w, a3);
            }
            gins[tid] = x + b2[tid] + ((a0 + a1) + (a2 + a3));
        }
        __syncthreads();

#pragma unroll
        for (int q = 0; q < 3; q++) {
            int g = tid + 256 * q;
            const float4* wr = (const float4*)(g2_Wih + (size_t)g * DMODEL);
            float a0 = 0.f, a1 = 0.f, a2 = 0.f, a3 = 0.f;
#pragma unroll 8
            for (int k = 0; k < 64; k++) {
                float4 wv = wr[k];
                float4 gv = *(const float4*)&gins[k * 4];
                a0 = fmaf(wv.x, gv.x, a0); a1 = fmaf(wv.y, gv.y, a1);
                a2 = fmaf(wv.z, gv.z, a2); a3 = fmaf(wv.w, gv.w, a3);
            }
            gi2[(size_t)t * G3 + g] = g2_bih[g] + ((a0 + a1) + (a2 + a3));
        }
        __syncthreads();
        if (tid == 0) st_rel(flags2 + (size_t)t * 32, 1);
    }
}

__global__ void __launch_bounds__(256, 1) __cluster_dims__(8, 1, 1)
k_tail(const float* __restrict__ gi1, const float* __restrict__ g1_Whh,
       const float* __restrict__ g1_bhh, float* __restrict__ ys1,
       const float* __restrict__ ln2_g, const float* __restrict__ ln2_b,
       const float* __restrict__ W1, const float* __restrict__ b1,
       const float* __restrict__ W2, const float* __restrict__ b2,
       const float* __restrict__ g2_Wih, const float* __restrict__ g2_bih,
       const float* __restrict__ g2_Whh, const float* __restrict__ g2_bhh,
       float* __restrict__ gi2, float* __restrict__ out_y,
       int* flags1, int* flags2)
{
    int cid = blockIdx.x >> 3;
    if (cid == 0) {
        gru_scan(gi1, g1_Whh, g1_bhh, ys1, flags1, nullptr);
    } else if (cid == 1) {
        gru_scan(gi2, g2_Whh, g2_bhh, out_y, nullptr, flags2);
    } else {
        worker_loop(blockIdx.x - 16, ys1, ln2_g, ln2_b, W1, b1, W2, b2,
                    g2_Wih, g2_bih, gi2, flags1, flags2);
    }
}

// ---------------- host orchestration ----------------
extern "C" void kernel_launch(void* const* d_in, const int* in_sizes, int n_in,
                              void* d_out, int out_size) {
    const float* inputs = (const float*)d_in[0];
    const float* r      = (const float*)d_in[1];
    const float* u      = (const float*)d_in[2];
    const float* v      = (const float*)d_in[3];
    const float* mem    = (const float*)d_in[4];
    const float* ln1_g  = (const float*)d_in[5];
    const float* ln1_b  = (const float*)d_in[6];
    const float* ln2_g  = (const float*)d_in[7];
    const float* ln2_b  = (const float*)d_in[8];
    const float* Wqkv   = (const float*)d_in[9];
    const float* bqkv   = (const float*)d_in[10];
    const float* Wr     = (const float*)d_in[11];
    const float* Wo     = (const float*)d_in[12];
    const float* bo     = (const float*)d_in[13];
    const float* g1_Wih = (const float*)d_in[14];
    const float* g1_Whh = (const float*)d_in[15];
    const float* g1_bih = (const float*)d_in[16];
    const float* g1_bhh = (const float*)d_in[17];
    const float* g2_Wih = (const float*)d_in[18];
    const float* g2_Whh = (const float*)d_in[19];
    const float* g2_bih = (const float*)d_in[20];
    const float* g2_bhh = (const float*)d_in[21];
    const float* W1     = (const float*)d_in[22];
    const float* b1     = (const float*)d_in[23];
    const float* W2     = (const float*)d_in[24];
    const float* b2     = (const float*)d_in[25];

    float* scr = nullptr;
    cudaGetSymbolAddress((void**)&scr, g_scr);

    float* CAT  = scr + OFF_CAT;
    float* QKV  = scr + OFF_QKV;
    float* RH   = scr + OFF_RH;
    float* QU   = scr + OFF_QU;
    float* QV   = scr + OFF_QV;
    float* KB   = scr + OFF_KB;
    float* RB   = scr + OFF_RB;
    float* VT   = scr + OFF_VT;
    float* AC   = scr + OFF_AC;
    float* BD   = scr + OFF_BD;
    float* P    = scr + OFF_P;
    float* AV   = scr + OFF_AV;
    float* Y    = scr + OFF_Y;
    float* GIN  = scr + OFF_GIN;
    float* GI   = scr + OFF_GI;
    float* YS1  = scr + OFF_YS1;
    float* GI2  = scr + OFF_GI2;
    int*   FLG1 = (int*)(scr + OFF_FLG);
    int*   FLG2 = FLG1 + 8 * 32;

    float* out_y    = (float*)d_out;
    float* out_attn = (float*)d_out + (size_t)QL * DMODEL;

    static int smax_cfg = 0;
    if (!smax_cfg) {
        cudaFuncSetAttribute(k_softmax8, cudaFuncAttributeMaxDynamicSharedMemorySize,
                             NH * KL * (int)sizeof(float));
        smax_cfg = 1;
    }

    cudaMemsetAsync(FLG1, 0, N_FLG * sizeof(int));

    k_concat<<<(KL*DMODEL)/256, 256>>>(mem, inputs, CAT);
    k_sgemm<<<dim3(G3/BN, KL/BM, 1), 256>>>(CAT, Wqkv, bqkv, nullptr, QKV,
        DMODEL, DMODEL, DMODEL, G3, 0, 0, 0, 0);
    k_sgemm<<<dim3(DMODEL/BN, KL/BM, 1), 256>>>(r, Wr, nullptr, nullptr, RH,
        DMODEL, DMODEL, DMODEL, DMODEL, 0, 0, 0, 0);
    k_prep_q<<<(NH*QL*DH)/256, 256>>>(QKV, u, v, QU, QV);
    k_prep_kv<<<(NH*KL*DH)/256, 256>>>(QKV, RH, KB, RB, VT);
    k_sgemm<<<dim3(KL/BN, QL/BM, NH), 256>>>(QU, KB, nullptr, nullptr, AC,
        DH, DH, DH, KL, (size_t)QL*DH, (size_t)KL*DH, (size_t)QL*KL, 0);
    k_sgemm<<<dim3(KL/BN, QL/BM, NH), 256>>>(QV, RB, nullptr, nullptr, BD,
        DH, DH, DH, KL, (size_t)QL*DH, (size_t)KL*DH, (size_t)QL*KL, 0);
    k_softmax8<<<QL, 256, NH*KL*sizeof(float)>>>(AC, BD, P, out_attn);
    k_av<<<dim3(QL/64, NH), 256>>>(P, VT, AV);
    k_sgemm<<<dim3(DMODEL/BN, QL/BM, 1), 256>>>(AV, Wo, bo, nullptr, Y,
        DMODEL, DMODEL, DMODEL, DMODEL, 0, 0, 0, 0);
    k_ln<<<QL, 256>>>(Y, ln1_g, ln1_b, inputs, GIN);
    k_sgemm<<<dim3(G3/BN, QL/BM, 1), 256>>>(GIN, g1_Wih, g1_bih, nullptr, GI,
        DMODEL, DMODEL, DMODEL, G3, 0, 0, 0, 0);
    // pipelined tail: 2 GRU clusters + 48 workers = 64 CTAs (single wave, one die)
    k_tail<<<16 + NWORK, 256>>>(GI, g1_Whh, g1_bhh, YS1,
                                ln2_g, ln2_b, W1, b1, W2, b2,
                                g2_Wih, g2_bih, g2_Whh, g2_bhh,
                                GI2, out_y, FLG1, FLG2);
}

// round 16
// speedup vs baseline: 1.1427x; 1.0515x over previous
#include <cuda_runtime.h>
#include <cstdint>
#include <cstddef>

// ---------------- problem constants ----------------
#define QL 1024
#define MLEN 1024
#define KL 2048
#define DMODEL 256
#define NH 8
#define DH 32
#define FF 1024
#define G3 768   // 3*DMODEL

typedef unsigned long long ull;

// ---------------- packed f32x2 helpers (GRU matvec only) ----------------
__device__ __forceinline__ void ffma2(ull& d, ull a, ull b) {
    asm("fma.rn.f32x2 %0, %1, %2, %0;" : "+l"(d) : "l"(a), "l"(b));
}
__device__ __forceinline__ float2 unpack2(ull v) {
    float lo, hi; asm("mov.b64 {%0,%1}, %2;" : "=f"(lo), "=f"(hi) : "l"(v));
    return make_float2(lo, hi);
}

// ---------------- scratch (floats) ----------------
#define N_CAT   (KL*DMODEL)
#define N_QKV   (KL*G3)
#define N_RH    (KL*DMODEL)
#define N_QU    (NH*QL*DH)
#define N_KB    (NH*KL*DH)
#define N_SC    ((size_t)NH*QL*KL)
#define N_ROW   (QL*DMODEL)
#define N_GI    (QL*G3)
#define N_MLPH  (QL*FF)

__device__ __align__(16) float g_scr[
    N_CAT + N_QKV + N_RH + 2*N_QU + 3*N_KB +
    3*N_SC +
    5*N_ROW + N_GI + 2*N_ROW + N_MLPH + 2*N_ROW + N_GI
];

#define OFF_CAT  ((size_t)0)
#define OFF_QKV  (OFF_CAT + N_CAT)
#define OFF_RH   (OFF_QKV + N_QKV)
#define OFF_QU   (OFF_RH  + N_RH)          // reused: BIASU (NH*KL floats)
#define OFF_QV   (OFF_QU  + N_QU)          // reused: BIASV (NH*KL floats)
#define OFF_KB   (OFF_QV  + N_QU)
#define OFF_RB   (OFF_KB  + N_KB)
#define OFF_VT   (OFF_RB  + N_KB)
#define OFF_AC   (OFF_VT  + N_KB)
#define OFF_BD   (OFF_AC  + N_SC)
#define OFF_P    (OFF_BD  + N_SC)
#define OFF_AV   (OFF_P   + N_SC)
#define OFF_Y    (OFF_AV  + N_ROW)
#define OFF_LN   (OFF_Y   + N_ROW)
#define OFF_GIN  (OFF_LN  + N_ROW)
#define OFF_GI   (OFF_GIN + N_ROW)
#define OFF_YS1  (OFF_GI  + N_GI)
#define OFF_LN2  (OFF_YS1 + N_ROW)
#define OFF_MLPH (OFF_LN2 + N_ROW)
#define OFF_MLPO (OFF_MLPH + N_MLPH)
#define OFF_GIN2 (OFF_MLPO + N_ROW)
#define OFF_GI2  (OFF_GIN2 + N_ROW)

// ---- fp32 SGEMM: C = A(MxK)*B(NxK)^T (+bias[bz*sBias + c])(+res)(+relu) ----
#define BM 64
#define BN 64
#define BKT 32

__global__ void __launch_bounds__(256)
k_sgemm(const float* __restrict__ A, const float* __restrict__ B,
        const float* __restrict__ bias, size_t sBias,
        const float* __restrict__ res,
        float* __restrict__ C,
        int K, int lda, int ldb, int ldc,
        size_t sA, size_t sB, size_t sC, int relu)
{
    int bz = blockIdx.z;
    A += (size_t)bz * sA;  B += (size_t)bz * sB;  C += (size_t)bz * sC;

    __shared__ float As[BKT][BM];
    __shared__ float Bs[BKT][BN];

    int tid = threadIdx.x;
    int row0 = blockIdx.y * BM, col0 = blockIdx.x * BN;
    int tx = tid & 15, ty = tid >> 4;
    int ar = tid >> 2;           // 0..63
    int ak = (tid & 3) * 8;      // 0,8,16,24

    const float* Aptr = A + (size_t)(row0 + ar) * lda + ak;
    const float* Bptr = B + (size_t)(col0 + ar) * ldb + ak;

    float acc[4][4];
#pragma unroll
    for (int i = 0; i < 4; i++)
#pragma unroll
        for (int j = 0; j < 4; j++) acc[i][j] = 0.f;

    int nt = K / BKT;
    for (int it = 0; it < nt; it++) {
        if (it) __syncthreads();
        float4 a0 = *(const float4*)(Aptr + (size_t)it * BKT);
        float4 a1 = *(const float4*)(Aptr + (size_t)it * BKT + 4);
        float4 b0 = *(const float4*)(Bptr + (size_t)it * BKT);
        float4 b1 = *(const float4*)(Bptr + (size_t)it * BKT + 4);
        As[ak+0][ar]=a0.x; As[ak+1][ar]=a0.y; As[ak+2][ar]=a0.z; As[ak+3][ar]=a0.w;
        As[ak+4][ar]=a1.x; As[ak+5][ar]=a1.y; As[ak+6][ar]=a1.z; As[ak+7][ar]=a1.w;
        Bs[ak+0][ar]=b0.x; Bs[ak+1][ar]=b0.y; Bs[ak+2][ar]=b0.z; Bs[ak+3][ar]=b0.w;
        Bs[ak+4][ar]=b1.x; Bs[ak+5][ar]=b1.y; Bs[ak+6][ar]=b1.z; Bs[ak+7][ar]=b1.w;
        __syncthreads();
#pragma unroll
        for (int kk = 0; kk < BKT; kk++) {
            float4 av4 = *(const float4*)&As[kk][ty*4];
            float4 bv4 = *(const float4*)&Bs[kk][tx*4];
            float a[4] = {av4.x, av4.y, av4.z, av4.w};
            float b[4] = {bv4.x, bv4.y, bv4.z, bv4.w};
#pragma unroll
            for (int i = 0; i < 4; i++)
#pragma unroll
                for (int j = 0; j < 4; j++)
                    acc[i][j] = fmaf(a[i], b[j], acc[i][j]);
        }
    }

#pragma unroll
    for (int i = 0; i < 4; i++) {
        int r = row0 + ty*4 + i;
#pragma unroll
        for (int j = 0; j < 4; j++) {
            int c = col0 + tx*4 + j;
            float v = acc[i][j];
            if (bias) v += bias[(size_t)bz * sBias + c];
            if (relu) v = v > 0.f ? v : 0.f;
            if (res)  v += res[(size_t)r * ldc + c];
            C[(size_t)r * ldc + c] = v;
        }
    }
}

// ---------------- small kernels ----------------
__global__ void k_concat(const float* __restrict__ mem, const float* __restrict__ inp,
                         float* __restrict__ cat)
{
    int idx = blockIdx.x * blockDim.x + threadIdx.x;
    int row = idx >> 8;
    cat[idx] = (row < MLEN) ? mem[idx] : inp[idx - MLEN * DMODEL];
}

// V^T only (KB/RB/QU/QV no longer materialized)
__global__ void k_prep_vt(const float* __restrict__ qkv, float* __restrict__ vt)
{
    int idx = blockIdx.x * blockDim.x + threadIdx.x;   // h*KL*DH + j*DH + d
    int h = idx >> 16;
    int rem = idx & 65535;
    int j = rem >> 5, d = rem & 31;
    int c = (h << 5) + d;
    vt[((size_t)h << 16) + ((size_t)d << 11) + j] = qkv[(size_t)j * G3 + 2*DMODEL + c];
}

// bias rows: bu[h,j] = u_h . k_{h,j}   bv[h,j] = v_h . rproj_{h,j}
__global__ void k_bias(const float* __restrict__ qkv, const float* __restrict__ rh,
                       const float* __restrict__ u, const float* __restrict__ v,
                       float* __restrict__ bu, float* __restrict__ bv)
{
    int idx = blockIdx.x * blockDim.x + threadIdx.x;   // 0..32767
    int sel = idx >> 14;
    int rem = idx & 16383;
    int h = rem >> 11, j = rem & 2047;
    const float* w = (sel ? v : u) + h * DH;
    const float* x = sel ? (rh + (size_t)j * DMODEL + h * DH)
                         : (qkv + (size_t)j * G3 + DMODEL + h * DH);
    float s = 0.f;
#pragma unroll
    for (int d = 0; d < DH; d++) s = fmaf(w[d], x[d], s);
    (sel ? bv : bu)[rem] = s;
}

__global__ void k_ln(const float* __restrict__ in, const float* __restrict__ g,
                     const float* __restrict__ b, const float* __restrict__ res,
                     float* __restrict__ out)
{
    __shared__ float red[256];
    int row = blockIdx.x, tid = threadIdx.x;
    float x = in[(size_t)row * DMODEL + tid];
    red[tid] = x; __syncthreads();
    for (int s = 128; s > 0; s >>= 1) { if (tid < s) red[tid] += red[tid + s]; __syncthreads(); }
    float mu = red[0] * (1.f / DMODEL);
    __syncthreads();
    float dx = x - mu;
    red[tid] = dx * dx; __syncthreads();
    for (int s = 128; s > 0; s >>= 1) { if (tid < s) red[tid] += red[tid + s]; __syncthreads(); }
    float var = red[0] * (1.f / DMODEL);
    float v = dx * rsqrtf(var + 1e-5f) * g[tid] + b[tid];
    if (res) v += res[(size_t)row * DMODEL + tid];
    out[(size_t)row * DMODEL + tid] = v;
}

// ---- softmax (8 heads per CTA) with rel-shift + mask; writes P (clamped) + attn ----
__global__ void __launch_bounds__(256)
k_softmax8(const float* __restrict__ AC, const float* __restrict__ BD,
           float* __restrict__ P, float* __restrict__ attn)
{
    extern __shared__ float sb[];     // 8 * 2048 floats (64 KB)
    __shared__ float red[256];
    int i = blockIdx.x, tid = threadIdx.x;
    int lim = i + MLEN;
    int kend = (i & ~63) + 64 + MLEN;           // k_av tile K bound
    if (kend > KL) kend = KL;
    const float scale = 0.17677669529663687f;   // 1/sqrt(32)

    for (int h = 0; h < NH; h++) {
        const float* ac = AC + ((size_t)h << 21) + ((size_t)i << 11);
        const float* bd = BD + ((size_t)h << 21) + ((size_t)i << 11) + (QL - 1 - i);
        float* row = sb + (h << 11);

        float mx = -1e30f;
        for (int j = tid; j <= lim; j += 256) {
            float s = (ac[j] + bd[j]) * scale;
            row[j] = s;
            mx = fmaxf(mx, s);
        }
        red[tid] = mx; __syncthreads();
        for (int s = 128; s > 0; s >>= 1) { if (tid < s) red[tid] = fmaxf(red[tid], red[tid+s]); __syncthreads(); }
        float mxv = red[0];
        __syncthreads();

        float sum = 0.f;
        for (int j = tid; j <= lim; j += 256) {
            float e = __expf(row[j] - mxv);
            row[j] = e;
            sum += e;
        }
        red[tid] = sum; __syncthreads();
        for (int s = 128; s > 0; s >>= 1) { if (tid < s) red[tid] += red[tid+s]; __syncthreads(); }
        float inv = 1.f / red[0];
        __syncthreads();

        float* p = P + ((size_t)h << 21) + ((size_t)i << 11);
        for (int j = tid; j < KL; j += 256) {
            float v = (j <= lim) ? row[j] * inv : 0.f;
            row[j] = v;
            if (j < kend) p[j] = v;   // cols >= kend never read by k_av
        }
    }
    __syncthreads();

    float* o = attn + (size_t)i * KL * NH;
    for (int j = tid; j < KL; j += 256) {
        float4 v0 = make_float4(sb[j], sb[2048 + j], sb[4096 + j], sb[6144 + j]);
        float4 v1 = make_float4(sb[8192 + j], sb[10240 + j], sb[12288 + j], sb[14336 + j]);
        float4* dst = (float4*)(o + (size_t)j * NH);
        dst[0] = v0;
        dst[1] = v1;
    }
}

// ---- AV: av[i, h*32+d] = sum_j P[h,i,j] * vt[h,d,j]; 64x32 tile, BK=32, 128 CTAs ----
__global__ void __launch_bounds__(256)
k_av(const float* __restrict__ P, const float* __restrict__ VT, float* __restrict__ AV)
{
    __shared__ float Ps[32][68];
    __shared__ float Vs[32][36];

    int bi = blockIdx.x, h = blockIdx.y;
    int i0 = bi * 64;
    int tid = threadIdx.x;
    int tx = tid & 7, ty = tid >> 3;

    const float* Ph = P  + ((size_t)h << 21);
    const float* Vh = VT + ((size_t)h << 16);

    int Kend = i0 + 64 + MLEN;
    if (Kend > KL) Kend = KL;
    int nt = Kend >> 5;

    int pr = tid >> 2;
    int pc = (tid & 3) * 8;
    int vd = tid >> 3;
    int vk = (tid & 7) * 4;

    const float* Pptr = Ph + (size_t)(i0 + pr) * KL + pc;
    const float* Vptr = Vh + (size_t)vd * KL + vk;

    float acc[2][4];
#pragma unroll
    for (int a = 0; a < 2; a++)
#pragma unroll
        for (int b = 0; b < 4; b++) acc[a][b] = 0.f;

    for (int it = 0; it < nt; it++) {
        if (it) __syncthreads();
        int j0 = it << 5;
        float4 p0 = *(const float4*)(Pptr + j0);
        float4 p1 = *(const float4*)(Pptr + j0 + 4);
        float4 v0 = *(const float4*)(Vptr + j0);
        Ps[pc+0][pr]=p0.x; Ps[pc+1][pr]=p0.y; Ps[pc+2][pr]=p0.z; Ps[pc+3][pr]=p0.w;
        Ps[pc+4][pr]=p1.x; Ps[pc+5][pr]=p1.y; Ps[pc+6][pr]=p1.z; Ps[pc+7][pr]=p1.w;
        Vs[vk+0][vd]=v0.x; Vs[vk+1][vd]=v0.y; Vs[vk+2][vd]=v0.z; Vs[vk+3][vd]=v0.w;
        __syncthreads();
#pragma unroll
        for (int kk = 0; kk < 32; kk++) {
            float2 pv = *(const float2*)&Ps[kk][ty*2];
            float4 vv = *(const float4*)&Vs[kk][tx*4];
            float pa[2] = {pv.x, pv.y};
            float vb[4] = {vv.x, vv.y, vv.z, vv.w};
#pragma unroll
            for (int a = 0; a < 2; a++)
#pragma unroll
                for (int b = 0; b < 4; b++)
                    acc[a][b] = fmaf(pa[a], vb[b], acc[a][b]);
        }
    }

#pragma unroll
    for (int a = 0; a < 2; a++) {
        int r = i0 + ty*2 + a;
#pragma unroll
        for (int b = 0; b < 4; b++) {
            int c = (h << 5) + tx*4 + b;
            AV[(size_t)r * DMODEL + c] = acc[a][b];
        }
    }
}

// -------- GRU scan: 8-CTA cluster, split barrier.cluster, register Whh, FFMA2 --------
__global__ void __launch_bounds__(192, 1) __cluster_dims__(8, 1, 1)
k_gru(const float* __restrict__ gi, const float* __restrict__ Whh,
      const float* __restrict__ bhh, float* __restrict__ ys)
{
    __shared__ float hbuf[512];   // double-buffered h (2 x 256)
    __shared__ float ghb[96];

    int tid = threadIdx.x;
    unsigned rank;
    asm("mov.u32 %0, %%cluster_ctarank;" : "=r"(rank));

    int rr = tid >> 1, hlf = tid & 1;
    int gate = rr >> 5, dl = rr & 31;
    int grow = gate * 256 + (int)rank * 32 + dl;
    const ulonglong2* wp = (const ulonglong2*)(Whh + (size_t)grow * DMODEL + hlf * 128);
    ulonglong2 w[32];
#pragma unroll
    for (int q = 0; q < 32; q++) w[q] = __ldg(&wp[q]);

    for (int i2 = tid; i2 < 512; i2 += 192) hbuf[i2] = 0.f;

    float bR = 0.f, bZ = 0.f, bN = 0.f;
    int gdim = 0;
    uint32_t hb_r[8];
    float ir = 0.f, iz = 0.f, inn = 0.f;
    if (tid < 32) {
        gdim = (int)rank * 32 + tid;
        bR = bhh[gdim]; bZ = bhh[256 + gdim]; bN = bhh[512 + gdim];
        uint32_t hb_l = (uint32_t)__cvta_generic_to_shared((void*)hbuf);
#pragma unroll
        for (int p = 0; p < 8; p++) {
            asm("mapa.shared::cluster.u32 %0, %1, %2;" : "=r"(hb_r[p]) : "r"(hb_l), "r"(p));
        }
        ir  = __ldg(gi + gdim);
        iz  = __ldg(gi + 256 + gdim);
        inn = __ldg(gi + 512 + gdim);
    }
    __syncthreads();
    asm volatile("barrier.cluster.arrive.aligned;" ::: "memory");
    asm volatile("barrier.cluster.wait.aligned;" ::: "memory");

#pragma unroll 1
    for (int t = 0; t < QL; t++) {
        float hprev = 0.f;
        if (tid < 32) hprev = hbuf[(t & 1) * 256 + gdim];

        const ulonglong2* h2 = (const ulonglong2*)(hbuf + (t & 1) * 256 + hlf * 128);
        ull acc0 = 0ull, acc1 = 0ull;
#pragma unroll
        for (int q = 0; q < 32; q++) {
            ulonglong2 hv = h2[q];
            ffma2(acc0, w[q].x, hv.x);
            ffma2(acc1, w[q].y, hv.y);
        }
        float2 a0 = unpack2(acc0), a1 = unpack2(acc1);
        float sum = (a0.x + a0.y) + (a1.x + a1.y);
        sum += __shfl_down_sync(0xffffffffu, sum, 1);
        if (!hlf) ghb[rr] = sum;
        __syncthreads();   // local matvec reads of slot (t&1) done; ghb ready

        float hnew = 0.f;
        if (tid < 32) {
            float hr = ghb[tid]      + bR;
            float hz = ghb[32 + tid] + bZ;
            float hn = ghb[64 + tid] + bN;
            float xr = ir + hr, xz = iz + hz;
            float rg = __fdividef(1.f, 1.f + __expf(-xr));
            float zg = __fdividef(1.f, 1.f + __expf(-xz));
            float xn = inn + rg * hn;
            float en = __expf(-2.f * fabsf(xn));
            float tg = (1.f - en) * __fdividef(1.f, 1.f + en);
            float ng = (xn >= 0.f) ? tg : -tg;
            hnew = (1.f - zg) * ng + zg * hprev;
            if (t < QL - 1) {
                uint32_t off = (uint32_t)(((t + 1) & 1) * 256 + gdim) * 4u;
#pragma unroll
                for (int p = 0; p < 8; p++) {
                    asm volatile("st.shared::cluster.f32 [%0], %1;"
                                 :: "r"(hb_r[p] + off), "f"(hnew) : "memory");
                }
            }
        }
        asm volatile("barrier.cluster.arrive.aligned;" ::: "memory");
        if (tid < 32) {
            ys[(size_t)t * DMODEL + gdim] = hnew;     // off critical path
            if (t + 1 < QL) {
                const float* g = gi + (size_t)(t + 1) * G3;
                ir  = __ldg(g + gdim);
                iz  = __ldg(g + 256 + gdim);
                inn = __ldg(g + 512 + gdim);
            }
        }
        asm volatile("barrier.cluster.wait.aligned;" ::: "memory");
    }
}

// ---------------- host orchestration ----------------
extern "C" void kernel_launch(void* const* d_in, const int* in_sizes, int n_in,
                              void* d_out, int out_size) {
    const float* inputs = (const float*)d_in[0];
    const float* r      = (const float*)d_in[1];
    const float* u      = (const float*)d_in[2];
    const float* v      = (const float*)d_in[3];
    const float* mem    = (const float*)d_in[4];
    const float* ln1_g  = (const float*)d_in[5];
    const float* ln1_b  = (const float*)d_in[6];
    const float* ln2_g  = (const float*)d_in[7];
    const float* ln2_b  = (const float*)d_in[8];
    const float* Wqkv   = (const float*)d_in[9];
    const float* bqkv   = (const float*)d_in[10];
    const float* Wr     = (const float*)d_in[11];
    const float* Wo     = (const float*)d_in[12];
    const float* bo     = (const float*)d_in[13];
    const float* g1_Wih = (const float*)d_in[14];
    const float* g1_Whh = (const float*)d_in[15];
    const float* g1_bih = (const float*)d_in[16];
    const float* g1_bhh = (const float*)d_in[17];
    const float* g2_Wih = (const float*)d_in[18];
    const float* g2_Whh = (const float*)d_in[19];
    const float* g2_bih = (const float*)d_in[20];
    const float* g2_bhh = (const float*)d_in[21];
    const float* W1     = (const float*)d_in[22];
    const float* b1     = (const float*)d_in[23];
    const float* W2     = (const float*)d_in[24];
    const float* b2     = (const float*)d_in[25];

    float* scr = nullptr;
    cudaGetSymbolAddress((void**)&scr, g_scr);

    float* CAT   = scr + OFF_CAT;
    float* QKV   = scr + OFF_QKV;
    float* RH    = scr + OFF_RH;
    float* BIASU = scr + OFF_QU;
    float* BIASV = scr + OFF_QV;
    float* VT    = scr + OFF_VT;
    float* AC    = scr + OFF_AC;
    float* BD    = scr + OFF_BD;
    float* P     = scr + OFF_P;
    float* AV    = scr + OFF_AV;
    float* Y     = scr + OFF_Y;
    float* GIN   = scr + OFF_GIN;
    float* GI    = scr + OFF_GI;
    float* YS1   = scr + OFF_YS1;
    float* LN2   = scr + OFF_LN2;
    float* MLPH  = scr + OFF_MLPH;
    float* GIN2  = scr + OFF_GIN2;
    float* GI2   = scr + OFF_GI2;

    float* out_y    = (float*)d_out;
    float* out_attn = (float*)d_out + (size_t)QL * DMODEL;

    static int smax_cfg = 0;
    if (!smax_cfg) {
        cudaFuncSetAttribute(k_softmax8, cudaFuncAttributeMaxDynamicSharedMemorySize,
                             NH * KL * (int)sizeof(float));
        smax_cfg = 1;
    }

    k_concat<<<(KL*DMODEL)/256, 256>>>(mem, inputs, CAT);
    k_sgemm<<<dim3(G3/BN, KL/BM, 1), 256>>>(CAT, Wqkv, bqkv, 0, nullptr, QKV,
        DMODEL, DMODEL, DMODEL, G3, 0, 0, 0, 0);
    k_sgemm<<<dim3(DMODEL/BN, KL/BM, 1), 256>>>(r, Wr, nullptr, 0, nullptr, RH,
        DMODEL, DMODEL, DMODEL, DMODEL, 0, 0, 0, 0);
    k_prep_vt<<<(NH*KL*DH)/256, 256>>>(QKV, VT);
    k_bias<<<(2*NH*KL)/256, 256>>>(QKV, RH, u, v, BIASU, BIASV);
    // AC[h] = Q_h @ K_h^T + (u_h.K_h)   — A,B read straight from qkv
    k_sgemm<<<dim3(KL/BN, QL/BM, NH), 256>>>(QKV + (size_t)MLEN*G3, QKV + DMODEL,
        BIASU, KL, nullptr, AC,
        DH, G3, G3, KL, 32, 32, (size_t)QL*KL, 0);
    // BDraw[h] = Q_h @ R_h^T + (v_h.R_h)
    k_sgemm<<<dim3(KL/BN, QL/BM, NH), 256>>>(QKV + (size_t)MLEN*G3, RH,
        BIASV, KL, nullptr, BD,
        DH, G3, DMODEL, KL, 32, 32, (size_t)QL*KL, 0);
    k_softmax8<<<QL, 256, NH*KL*sizeof(float)>>>(AC, BD, P, out_attn);
    k_av<<<dim3(QL/64, NH), 256>>>(P, VT, AV);
    k_sgemm<<<dim3(DMODEL/BN, QL/BM, 1), 256>>>(AV, Wo, bo, 0, nullptr, Y,
        DMODEL, DMODEL, DMODEL, DMODEL, 0, 0, 0, 0);
    k_ln<<<QL, 256>>>(Y, ln1_g, ln1_b, inputs, GIN);
    k_sgemm<<<dim3(G3/BN, QL/BM, 1), 256>>>(GIN, g1_Wih, g1_bih, 0, nullptr, GI,
        DMODEL, DMODEL, DMODEL, G3, 0, 0, 0, 0);
    k_gru<<<8, 192>>>(GI, g1_Whh, g1_bhh, YS1);
    k_ln<<<QL, 256>>>(YS1, ln2_g, ln2_b, nullptr, LN2);
    k_sgemm<<<dim3(FF/BN, QL/BM, 1), 256>>>(LN2, W1, b1, 0, nullptr, MLPH,
        DMODEL, DMODEL, DMODEL, FF, 0, 0, 0, 1);
    k_sgemm<<<dim3(DMODEL/BN, QL/BM, 1), 256>>>(MLPH, W2, b2, 0, YS1, GIN2,
        FF, FF, FF, DMODEL, 0, 0, 0, 0);
    k_sgemm<<<dim3(G3/BN, QL/BM, 1), 256>>>(GIN2, g2_Wih, g2_bih, 0, nullptr, GI2,
        DMODEL, DMODEL, DMODEL, G3, 0, 0, 0, 0);
    k_gru<<<8, 192>>>(GI2, g2_Whh, g2_bhh, out_y);
}

// round 17
// speedup vs baseline: 1.1517x; 1.0079x over previous
#include <cuda_runtime.h>
#include <cstdint>
#include <cstddef>

// ---------------- problem constants ----------------
#define QL 1024
#define MLEN 1024
#define KL 2048
#define DMODEL 256
#define NH 8
#define DH 32
#define FF 1024
#define G3 768   // 3*DMODEL

typedef unsigned long long ull;

// ---------------- packed f32x2 helpers (GRU matvec only) ----------------
__device__ __forceinline__ void ffma2(ull& d, ull a, ull b) {
    asm("fma.rn.f32x2 %0, %1, %2, %0;" : "+l"(d) : "l"(a), "l"(b));
}
__device__ __forceinline__ float2 unpack2(ull v) {
    float lo, hi; asm("mov.b64 {%0,%1}, %2;" : "=f"(lo), "=f"(hi) : "l"(v));
    return make_float2(lo, hi);
}
__device__ __forceinline__ float tanh_fast(float x) {
    float y; asm("tanh.approx.f32 %0, %1;" : "=f"(y) : "f"(x)); return y;
}

// ---------------- scratch (floats) ----------------
#define N_CAT   (KL*DMODEL)
#define N_QKV   (KL*G3)
#define N_RH    (KL*DMODEL)
#define N_QU    (NH*QL*DH)
#define N_KB    (NH*KL*DH)
#define N_SC    ((size_t)NH*QL*KL)
#define N_ROW   (QL*DMODEL)
#define N_GI    (QL*G3)
#define N_MLPH  (QL*FF)

__device__ __align__(16) float g_scr[
    N_CAT + N_QKV + N_RH + 2*N_QU + 3*N_KB +
    3*N_SC +
    5*N_ROW + N_GI + 2*N_ROW + N_MLPH + 2*N_ROW + N_GI
];

#define OFF_CAT  ((size_t)0)
#define OFF_QKV  (OFF_CAT + N_CAT)
#define OFF_RH   (OFF_QKV + N_QKV)
#define OFF_QU   (OFF_RH  + N_RH)          // reused: BIASU (NH*KL floats)
#define OFF_QV   (OFF_QU  + N_QU)          // reused: BIASV (NH*KL floats)
#define OFF_KB   (OFF_QV  + N_QU)
#define OFF_RB   (OFF_KB  + N_KB)
#define OFF_VT   (OFF_RB  + N_KB)
#define OFF_AC   (OFF_VT  + N_KB)
#define OFF_BD   (OFF_AC  + N_SC)
#define OFF_P    (OFF_BD  + N_SC)
#define OFF_AV   (OFF_P   + N_SC)
#define OFF_Y    (OFF_AV  + N_ROW)
#define OFF_LN   (OFF_Y   + N_ROW)
#define OFF_GIN  (OFF_LN  + N_ROW)
#define OFF_GI   (OFF_GIN + N_ROW)
#define OFF_YS1  (OFF_GI  + N_GI)
#define OFF_LN2  (OFF_YS1 + N_ROW)
#define OFF_MLPH (OFF_LN2 + N_ROW)
#define OFF_MLPO (OFF_MLPH + N_MLPH)
#define OFF_GIN2 (OFF_MLPO + N_ROW)
#define OFF_GI2  (OFF_GIN2 + N_ROW)

// ---- fp32 SGEMM: C = A(MxK)*B(NxK)^T (+bias[bz*sBias + c])(+res)(+relu) ----
#define BM 64
#define BN 64
#define BKT 32

__global__ void __launch_bounds__(256)
k_sgemm(const float* __restrict__ A, const float* __restrict__ B,
        const float* __restrict__ bias, size_t sBias,
        const float* __restrict__ res,
        float* __restrict__ C,
        int K, int lda, int ldb, int ldc,
        size_t sA, size_t sB, size_t sC, int relu)
{
    int bz = blockIdx.z;
    A += (size_t)bz * sA;  B += (size_t)bz * sB;  C += (size_t)bz * sC;

    __shared__ float As[BKT][BM];
    __shared__ float Bs[BKT][BN];

    int tid = threadIdx.x;
    int row0 = blockIdx.y * BM, col0 = blockIdx.x * BN;
    int tx = tid & 15, ty = tid >> 4;
    int ar = tid >> 2;           // 0..63
    int ak = (tid & 3) * 8;      // 0,8,16,24

    const float* Aptr = A + (size_t)(row0 + ar) * lda + ak;
    const float* Bptr = B + (size_t)(col0 + ar) * ldb + ak;

    float acc[4][4];
#pragma unroll
    for (int i = 0; i < 4; i++)
#pragma unroll
        for (int j = 0; j < 4; j++) acc[i][j] = 0.f;

    int nt = K / BKT;
    for (int it = 0; it < nt; it++) {
        if (it) __syncthreads();
        float4 a0 = *(const float4*)(Aptr + (size_t)it * BKT);
        float4 a1 = *(const float4*)(Aptr + (size_t)it * BKT + 4);
        float4 b0 = *(const float4*)(Bptr + (size_t)it * BKT);
        float4 b1 = *(const float4*)(Bptr + (size_t)it * BKT + 4);
        As[ak+0][ar]=a0.x; As[ak+1][ar]=a0.y; As[ak+2][ar]=a0.z; As[ak+3][ar]=a0.w;
        As[ak+4][ar]=a1.x; As[ak+5][ar]=a1.y; As[ak+6][ar]=a1.z; As[ak+7][ar]=a1.w;
        Bs[ak+0][ar]=b0.x; Bs[ak+1][ar]=b0.y; Bs[ak+2][ar]=b0.z; Bs[ak+3][ar]=b0.w;
        Bs[ak+4][ar]=b1.x; Bs[ak+5][ar]=b1.y; Bs[ak+6][ar]=b1.z; Bs[ak+7][ar]=b1.w;
        __syncthreads();
#pragma unroll
        for (int kk = 0; kk < BKT; kk++) {
            float4 av4 = *(const float4*)&As[kk][ty*4];
            float4 bv4 = *(const float4*)&Bs[kk][tx*4];
            float a[4] = {av4.x, av4.y, av4.z, av4.w};
            float b[4] = {bv4.x, bv4.y, bv4.z, bv4.w};
#pragma unroll
            for (int i = 0; i < 4; i++)
#pragma unroll
                for (int j = 0; j < 4; j++)
                    acc[i][j] = fmaf(a[i], b[j], acc[i][j]);
        }
    }

#pragma unroll
    for (int i = 0; i < 4; i++) {
        int r = row0 + ty*4 + i;
#pragma unroll
        for (int j = 0; j < 4; j++) {
            int c = col0 + tx*4 + j;
            float v = acc[i][j];
            if (bias) v += bias[(size_t)bz * sBias + c];
            if (relu) v = v > 0.f ? v : 0.f;
            if (res)  v += res[(size_t)r * ldc + c];
            C[(size_t)r * ldc + c] = v;
        }
    }
}

// ---------------- small kernels ----------------
__global__ void k_concat(const float* __restrict__ mem, const float* __restrict__ inp,
                         float* __restrict__ cat)
{
    int idx = blockIdx.x * blockDim.x + threadIdx.x;
    int row = idx >> 8;
    cat[idx] = (row < MLEN) ? mem[idx] : inp[idx - MLEN * DMODEL];
}

// V^T only
__global__ void k_prep_vt(const float* __restrict__ qkv, float* __restrict__ vt)
{
    int idx = blockIdx.x * blockDim.x + threadIdx.x;   // h*KL*DH + j*DH + d
    int h = idx >> 16;
    int rem = idx & 65535;
    int j = rem >> 5, d = rem & 31;
    int c = (h << 5) + d;
    vt[((size_t)h << 16) + ((size_t)d << 11) + j] = qkv[(size_t)j * G3 + 2*DMODEL + c];
}

// bias rows: bu[h,j] = u_h . k_{h,j}   bv[h,j] = v_h . rproj_{h,j}
__global__ void k_bias(const float* __restrict__ qkv, const float* __restrict__ rh,
                       const float* __restrict__ u, const float* __restrict__ v,
                       float* __restrict__ bu, float* __restrict__ bv)
{
    int idx = blockIdx.x * blockDim.x + threadIdx.x;   // 0..32767
    int sel = idx >> 14;
    int rem = idx & 16383;
    int h = rem >> 11, j = rem & 2047;
    const float* w = (sel ? v : u) + h * DH;
    const float* x = sel ? (rh + (size_t)j * DMODEL + h * DH)
                         : (qkv + (size_t)j * G3 + DMODEL + h * DH);
    float s = 0.f;
#pragma unroll
    for (int d = 0; d < DH; d++) s = fmaf(w[d], x[d], s);
    (sel ? bv : bu)[rem] = s;
}

__global__ void k_ln(const float* __restrict__ in, const float* __restrict__ g,
                     const float* __restrict__ b, const float* __restrict__ res,
                     float* __restrict__ out)
{
    __shared__ float red[256];
    int row = blockIdx.x, tid = threadIdx.x;
    float x = in[(size_t)row * DMODEL + tid];
    red[tid] = x; __syncthreads();
    for (int s = 128; s > 0; s >>= 1) { if (tid < s) red[tid] += red[tid + s]; __syncthreads(); }
    float mu = red[0] * (1.f / DMODEL);
    __syncthreads();
    float dx = x - mu;
    red[tid] = dx * dx; __syncthreads();
    for (int s = 128; s > 0; s >>= 1) { if (tid < s) red[tid] += red[tid + s]; __syncthreads(); }
    float var = red[0] * (1.f / DMODEL);
    float v = dx * rsqrtf(var + 1e-5f) * g[tid] + b[tid];
    if (res) v += res[(size_t)row * DMODEL + tid];
    out[(size_t)row * DMODEL + tid] = v;
}

// ---- softmax (8 heads per CTA) with rel-shift + mask; writes P (clamped) + attn ----
__global__ void __launch_bounds__(256)
k_softmax8(const float* __restrict__ AC, const float* __restrict__ BD,
           float* __restrict__ P, float* __restrict__ attn)
{
    extern __shared__ float sb[];     // 8 * 2048 floats (64 KB)
    __shared__ float red[256];
    int i = blockIdx.x, tid = threadIdx.x;
    int lim = i + MLEN;
    int kend = (i & ~63) + 64 + MLEN;           // k_av tile K bound
    if (kend > KL) kend = KL;
    const float scale = 0.17677669529663687f;   // 1/sqrt(32)

    for (int h = 0; h < NH; h++) {
        const float* ac = AC + ((size_t)h << 21) + ((size_t)i << 11);
        const float* bd = BD + ((size_t)h << 21) + ((size_t)i << 11) + (QL - 1 - i);
        float* row = sb + (h << 11);

        float mx = -1e30f;
        for (int j = tid; j <= lim; j += 256) {
            float s = (ac[j] + bd[j]) * scale;
            row[j] = s;
            mx = fmaxf(mx, s);
        }
        red[tid] = mx; __syncthreads();
        for (int s = 128; s > 0; s >>= 1) { if (tid < s) red[tid] = fmaxf(red[tid], red[tid+s]); __syncthreads(); }
        float mxv = red[0];
        __syncthreads();

        float sum = 0.f;
        for (int j = tid; j <= lim; j += 256) {
            float e = __expf(row[j] - mxv);
            row[j] = e;
            sum += e;
        }
        red[tid] = sum; __syncthreads();
        for (int s = 128; s > 0; s >>= 1) { if (tid < s) red[tid] += red[tid+s]; __syncthreads(); }
        float inv = 1.f / red[0];
        __syncthreads();

        float* p = P + ((size_t)h << 21) + ((size_t)i << 11);
        for (int j = tid; j < KL; j += 256) {
            float v = (j <= lim) ? row[j] * inv : 0.f;
            row[j] = v;
            if (j < kend) p[j] = v;
        }
    }
    __syncthreads();

    float* o = attn + (size_t)i * KL * NH;
    for (int j = tid; j < KL; j += 256) {
        float4 v0 = make_float4(sb[j], sb[2048 + j], sb[4096 + j], sb[6144 + j]);
        float4 v1 = make_float4(sb[8192 + j], sb[10240 + j], sb[12288 + j], sb[14336 + j]);
        float4* dst = (float4*)(o + (size_t)j * NH);
        dst[0] = v0;
        dst[1] = v1;
    }
}

// ---- AV: av[i, h*32+d] = sum_j P[h,i,j] * vt[h,d,j]; 64x32 tile, BK=32, 128 CTAs ----
__global__ void __launch_bounds__(256)
k_av(const float* __restrict__ P, const float* __restrict__ VT, float* __restrict__ AV)
{
    __shared__ float Ps[32][68];
    __shared__ float Vs[32][36];

    int bi = blockIdx.x, h = blockIdx.y;
    int i0 = bi * 64;
    int tid = threadIdx.x;
    int tx = tid & 7, ty = tid >> 3;

    const float* Ph = P  + ((size_t)h << 21);
    const float* Vh = VT + ((size_t)h << 16);

    int Kend = i0 + 64 + MLEN;
    if (Kend > KL) Kend = KL;
    int nt = Kend >> 5;

    int pr = tid >> 2;
    int pc = (tid & 3) * 8;
    int vd = tid >> 3;
    int vk = (tid & 7) * 4;

    const float* Pptr = Ph + (size_t)(i0 + pr) * KL + pc;
    const float* Vptr = Vh + (size_t)vd * KL + vk;

    float acc[2][4];
#pragma unroll
    for (int a = 0; a < 2; a++)
#pragma unroll
        for (int b = 0; b < 4; b++) acc[a][b] = 0.f;

    for (int it = 0; it < nt; it++) {
        if (it) __syncthreads();
        int j0 = it << 5;
        float4 p0 = *(const float4*)(Pptr + j0);
        float4 p1 = *(const float4*)(Pptr + j0 + 4);
        float4 v0 = *(const float4*)(Vptr + j0);
        Ps[pc+0][pr]=p0.x; Ps[pc+1][pr]=p0.y; Ps[pc+2][pr]=p0.z; Ps[pc+3][pr]=p0.w;
        Ps[pc+4][pr]=p1.x; Ps[pc+5][pr]=p1.y; Ps[pc+6][pr]=p1.z; Ps[pc+7][pr]=p1.w;
        Vs[vk+0][vd]=v0.x; Vs[vk+1][vd]=v0.y; Vs[vk+2][vd]=v0.z; Vs[vk+3][vd]=v0.w;
        __syncthreads();
#pragma unroll
        for (int kk = 0; kk < 32; kk++) {
            float2 pv = *(const float2*)&Ps[kk][ty*2];
            float4 vv = *(const float4*)&Vs[kk][tx*4];
            float pa[2] = {pv.x, pv.y};
            float vb[4] = {vv.x, vv.y, vv.z, vv.w};
#pragma unroll
            for (int a = 0; a < 2; a++)
#pragma unroll
                for (int b = 0; b < 4; b++)
                    acc[a][b] = fmaf(pa[a], vb[b], acc[a][b]);
        }
    }

#pragma unroll
    for (int a = 0; a < 2; a++) {
        int r = i0 + ty*2 + a;
#pragma unroll
        for (int b = 0; b < 4; b++) {
            int c = (h << 5) + tx*4 + b;
            AV[(size_t)r * DMODEL + c] = acc[a][b];
        }
    }
}

// -------- GRU scan: 8-CTA cluster, split barrier.cluster, register Whh, FFMA2,
//          HW tanh.approx gate chain --------
__global__ void __launch_bounds__(192, 1) __cluster_dims__(8, 1, 1)
k_gru(const float* __restrict__ gi, const float* __restrict__ Whh,
      const float* __restrict__ bhh, float* __restrict__ ys)
{
    __shared__ float hbuf[512];   // double-buffered h (2 x 256)
    __shared__ float ghb[96];

    int tid = threadIdx.x;
    unsigned rank;
    asm("mov.u32 %0, %%cluster_ctarank;" : "=r"(rank));

    int rr = tid >> 1, hlf = tid & 1;
    int gate = rr >> 5, dl = rr & 31;
    int grow = gate * 256 + (int)rank * 32 + dl;
    const ulonglong2* wp = (const ulonglong2*)(Whh + (size_t)grow * DMODEL + hlf * 128);
    ulonglong2 w[32];
#pragma unroll
    for (int q = 0; q < 32; q++) w[q] = __ldg(&wp[q]);

    for (int i2 = tid; i2 < 512; i2 += 192) hbuf[i2] = 0.f;

    float bR = 0.f, bZ = 0.f, bN = 0.f;
    int gdim = 0;
    uint32_t hb_r[8];
    float ir = 0.f, iz = 0.f, inn = 0.f;
    if (tid < 32) {
        gdim = (int)rank * 32 + tid;
        bR = bhh[gdim]; bZ = bhh[256 + gdim]; bN = bhh[512 + gdim];
        uint32_t hb_l = (uint32_t)__cvta_generic_to_shared((void*)hbuf);
#pragma unroll
        for (int p = 0; p < 8; p++) {
            asm("mapa.shared::cluster.u32 %0, %1, %2;" : "=r"(hb_r[p]) : "r"(hb_l), "r"(p));
        }
        ir  = __ldg(gi + gdim);
        iz  = __ldg(gi + 256 + gdim);
        inn = __ldg(gi + 512 + gdim);
    }
    __syncthreads();
    asm volatile("barrier.cluster.arrive.aligned;" ::: "memory");
    asm volatile("barrier.cluster.wait.aligned;" ::: "memory");

#pragma unroll 1
    for (int t = 0; t < QL; t++) {
        float hprev = 0.f;
        if (tid < 32) hprev = hbuf[(t & 1) * 256 + gdim];

        const ulonglong2* h2 = (const ulonglong2*)(hbuf + (t & 1) * 256 + hlf * 128);
        ull acc0 = 0ull, acc1 = 0ull;
#pragma unroll
        for (int q = 0; q < 32; q++) {
            ulonglong2 hv = h2[q];
            ffma2(acc0, w[q].x, hv.x);
            ffma2(acc1, w[q].y, hv.y);
        }
        float2 a0 = unpack2(acc0), a1 = unpack2(acc1);
        float sum = (a0.x + a0.y) + (a1.x + a1.y);
        sum += __shfl_down_sync(0xffffffffu, sum, 1);
        if (!hlf) ghb[rr] = sum;
        __syncthreads();   // local matvec reads of slot (t&1) done; ghb ready

        float hnew = 0.f;
        if (tid < 32) {
            float hr = ghb[tid]      + bR;
            float hz = ghb[32 + tid] + bZ;
            float hn = ghb[64 + tid] + bN;
            float xr = ir + hr, xz = iz + hz;
            // sigmoid via HW tanh: s(x) = 0.5*tanh(0.5x)+0.5
            float rg = fmaf(tanh_fast(0.5f * xr), 0.5f, 0.5f);
            float zg = fmaf(tanh_fast(0.5f * xz), 0.5f, 0.5f);
            float xn = fmaf(rg, hn, inn);
            float ng = tanh_fast(xn);
            hnew = fmaf(zg, hprev - ng, ng);   // (1-zg)*ng + zg*hprev
            if (t < QL - 1) {
                uint32_t off = (uint32_t)(((t + 1) & 1) * 256 + gdim) * 4u;
#pragma unroll
                for (int p = 0; p < 8; p++) {
                    asm volatile("st.shared::cluster.f32 [%0], %1;"
                                 :: "r"(hb_r[p] + off), "f"(hnew) : "memory");
                }
            }
        }
        asm volatile("barrier.cluster.arrive.aligned;" ::: "memory");
        if (tid < 32) {
            ys[(size_t)t * DMODEL + gdim] = hnew;     // off critical path
            if (t + 1 < QL) {
                const float* g = gi + (size_t)(t + 1) * G3;
                ir  = __ldg(g + gdim);
                iz  = __ldg(g + 256 + gdim);
                inn = __ldg(g + 512 + gdim);
            }
        }
        asm volatile("barrier.cluster.wait.aligned;" ::: "memory");
    }
}

// ---------------- host orchestration ----------------
extern "C" void kernel_launch(void* const* d_in, const int* in_sizes, int n_in,
                              void* d_out, int out_size) {
    const float* inputs = (const float*)d_in[0];
    const float* r      = (const float*)d_in[1];
    const float* u      = (const float*)d_in[2];
    const float* v      = (const float*)d_in[3];
    const float* mem    = (const float*)d_in[4];
    const float* ln1_g  = (const float*)d_in[5];
    const float* ln1_b  = (const float*)d_in[6];
    const float* ln2_g  = (const float*)d_in[7];
    const float* ln2_b  = (const float*)d_in[8];
    const float* Wqkv   = (const float*)d_in[9];
    const float* bqkv   = (const float*)d_in[10];
    const float* Wr     = (const float*)d_in[11];
    const float* Wo     = (const float*)d_in[12];
    const float* bo     = (const float*)d_in[13];
    const float* g1_Wih = (const float*)d_in[14];
    const float* g1_Whh = (const float*)d_in[15];
    const float* g1_bih = (const float*)d_in[16];
    const float* g1_bhh = (const float*)d_in[17];
    const float* g2_Wih = (const float*)d_in[18];
    const float* g2_Whh = (const float*)d_in[19];
    const float* g2_bih = (const float*)d_in[20];
    const float* g2_bhh = (const float*)d_in[21];
    const float* W1     = (const float*)d_in[22];
    const float* b1     = (const float*)d_in[23];
    const float* W2     = (const float*)d_in[24];
    const float* b2     = (const float*)d_in[25];

    float* scr = nullptr;
    cudaGetSymbolAddress((void**)&scr, g_scr);

    float* CAT   = scr + OFF_CAT;
    float* QKV   = scr + OFF_QKV;
    float* RH    = scr + OFF_RH;
    float* BIASU = scr + OFF_QU;
    float* BIASV = scr + OFF_QV;
    float* VT    = scr + OFF_VT;
    float* AC    = scr + OFF_AC;
    float* BD    = scr + OFF_BD;
    float* P     = scr + OFF_P;
    float* AV    = scr + OFF_AV;
    float* Y     = scr + OFF_Y;
    float* GIN   = scr + OFF_GIN;
    float* GI    = scr + OFF_GI;
    float* YS1   = scr + OFF_YS1;
    float* LN2   = scr + OFF_LN2;
    float* MLPH  = scr + OFF_MLPH;
    float* GIN2  = scr + OFF_GIN2;
    float* GI2   = scr + OFF_GI2;

    float* out_y    = (float*)d_out;
    float* out_attn = (float*)d_out + (size_t)QL * DMODEL;

    static int smax_cfg = 0;
    if (!smax_cfg) {
        cudaFuncSetAttribute(k_softmax8, cudaFuncAttributeMaxDynamicSharedMemorySize,
                             NH * KL * (int)sizeof(float));
        smax_cfg = 1;
    }

    k_concat<<<(KL*DMODEL)/256, 256>>>(mem, inputs, CAT);
    k_sgemm<<<dim3(G3/BN, KL/BM, 1), 256>>>(CAT, Wqkv, bqkv, 0, nullptr, QKV,
        DMODEL, DMODEL, DMODEL, G3, 0, 0, 0, 0);
    k_sgemm<<<dim3(DMODEL/BN, KL/BM, 1), 256>>>(r, Wr, nullptr, 0, nullptr, RH,
        DMODEL, DMODEL, DMODEL, DMODEL, 0, 0, 0, 0);
    k_prep_vt<<<(NH*KL*DH)/256, 256>>>(QKV, VT);
    k_bias<<<(2*NH*KL)/256, 256>>>(QKV, RH, u, v, BIASU, BIASV);
    // AC[h] = Q_h @ K_h^T + (u_h.K_h)
    k_sgemm<<<dim3(KL/BN, QL/BM, NH), 256>>>(QKV + (size_t)MLEN*G3, QKV + DMODEL,
        BIASU, KL, nullptr, AC,
        DH, G3, G3, KL, 32, 32, (size_t)QL*KL, 0);
    // BDraw[h] = Q_h @ R_h^T + (v_h.R_h)
    k_sgemm<<<dim3(KL/BN, QL/BM, NH), 256>>>(QKV + (size_t)MLEN*G3, RH,
        BIASV, KL, nullptr, BD,
        DH, G3, DMODEL, KL, 32, 32, (size_t)QL*KL, 0);
    k_softmax8<<<QL, 256, NH*KL*sizeof(float)>>>(AC, BD, P, out_attn);
    k_av<<<dim3(QL/64, NH), 256>>>(P, VT, AV);
    k_sgemm<<<dim3(DMODEL/BN, QL/BM, 1), 256>>>(AV, Wo, bo, 0, nullptr, Y,
        DMODEL, DMODEL, DMODEL, DMODEL, 0, 0, 0, 0);
    k_ln<<<QL, 256>>>(Y, ln1_g, ln1_b, inputs, GIN);
    k_sgemm<<<dim3(G3/BN, QL/BM, 1), 256>>>(GIN, g1_Wih, g1_bih, 0, nullptr, GI,
        DMODEL, DMODEL, DMODEL, G3, 0, 0, 0, 0);
    k_gru<<<8, 192>>>(GI, g1_Whh, g1_bhh, YS1);
    k_ln<<<QL, 256>>>(YS1, ln2_g, ln2_b, nullptr, LN2);
    k_sgemm<<<dim3(FF/BN, QL/BM, 1), 256>>>(LN2, W1, b1, 0, nullptr, MLPH,
        DMODEL, DMODEL, DMODEL, FF, 0, 0, 0, 1);
    k_sgemm<<<dim3(DMODEL/BN, QL/BM, 1), 256>>>(MLPH, W2, b2, 0, YS1, GIN2,
        FF, FF, FF, DMODEL, 0, 0, 0, 0);
    k_sgemm<<<dim3(G3/BN, QL/BM, 1), 256>>>(GIN2, g2_Wih, g2_bih, 0, nullptr, GI2,
        DMODEL, DMODEL, DMODEL, G3, 0, 0, 0, 0);
    k_gru<<<8, 192>>>(GI2, g2_Whh, g2_bhh, out_y);
}